// round 6
// baseline (speedup 1.0000x reference)
#include <cuda_runtime.h>
#include <math.h>

#define BATCH 4
#define SEQ   2048
#define DM    1024
#define NH    16
#define HD    64
#define MTOT  (BATCH*SEQ)   // 8192

// Scratch (static __device__ arrays — allocation-guard safe)
__device__ float g_q[(size_t)BATCH*NH*SEQ*HD];      // [(b*NH+h)][s][d]
__device__ float g_k[(size_t)BATCH*NH*SEQ*HD];
__device__ float g_v[(size_t)BATCH*NH*SEQ*HD];
__device__ float g_attn[(size_t)MTOT*DM];           // [b*SEQ+s][D]

// ---------------------------------------------------------------------------
// Kernel 1: QKV GEMM (C[m,e] = sum_d X[m,d] * Wqkv[e,d]), scatter to head
// layout. M=8192, N=3072, K=1024. 128x128 tile, 8x8 per thread, BK=8.
// ---------------------------------------------------------------------------
__global__ __launch_bounds__(256) void qkv_gemm(const float* __restrict__ X,
                                                const float* __restrict__ W) {
    __shared__ float As[8][128];
    __shared__ float Bs[8][128];
    const int tid = threadIdx.x;
    const int tx  = tid & 15;
    const int ty  = tid >> 4;
    const int m0  = blockIdx.y * 128;
    const int n0  = blockIdx.x * 128;
    const int lrow = tid >> 1;
    const int lk   = (tid & 1) << 2;
    const float* Ap = X + (size_t)(m0 + lrow) * DM + lk;
    const float* Bp = W + (size_t)(n0 + lrow) * DM + lk;

    float acc[8][8];
#pragma unroll
    for (int i = 0; i < 8; i++)
#pragma unroll
        for (int j = 0; j < 8; j++) acc[i][j] = 0.f;

    for (int kt = 0; kt < DM; kt += 8) {
        float4 a = *(const float4*)(Ap + kt);
        float4 b = *(const float4*)(Bp + kt);
        __syncthreads();
        As[lk+0][lrow] = a.x; As[lk+1][lrow] = a.y; As[lk+2][lrow] = a.z; As[lk+3][lrow] = a.w;
        Bs[lk+0][lrow] = b.x; Bs[lk+1][lrow] = b.y; Bs[lk+2][lrow] = b.z; Bs[lk+3][lrow] = b.w;
        __syncthreads();
#pragma unroll
        for (int k = 0; k < 8; k++) {
            float4 a0 = *(const float4*)&As[k][ty*8];
            float4 a1 = *(const float4*)&As[k][ty*8+4];
            float4 b0 = *(const float4*)&Bs[k][tx*8];
            float4 b1 = *(const float4*)&Bs[k][tx*8+4];
            float ar[8] = {a0.x,a0.y,a0.z,a0.w,a1.x,a1.y,a1.z,a1.w};
            float br[8] = {b0.x,b0.y,b0.z,b0.w,b1.x,b1.y,b1.z,b1.w};
#pragma unroll
            for (int i = 0; i < 8; i++)
#pragma unroll
                for (int j = 0; j < 8; j++)
                    acc[i][j] = fmaf(ar[i], br[j], acc[i][j]);
        }
    }

    const int nbase = n0 + tx*8;
    const int which = nbase >> 10;
    const int h     = (nbase & 1023) >> 6;
    const int dd0   = nbase & 63;
    float* dst = (which == 0) ? g_q : (which == 1) ? g_k : g_v;

#pragma unroll
    for (int i = 0; i < 8; i++) {
        int m = m0 + ty*8 + i;
        int b = m >> 11;
        int s = m & 2047;
        size_t base = ((((size_t)b*NH + h)*SEQ + s)*HD) + dd0;
        *(float4*)(dst + base)     = make_float4(acc[i][0],acc[i][1],acc[i][2],acc[i][3]);
        *(float4*)(dst + base + 4) = make_float4(acc[i][4],acc[i][5],acc[i][6],acc[i][7]);
    }
}

// ---------------------------------------------------------------------------
// Kernel 1b: RoPE in place — NEGATED-SIN interleaved convention:
//   out[2p]   = x[2p]*cos + x[2p+1]*sin
//   out[2p+1] = x[2p+1]*cos - x[2p]*sin,   angle = s * theta^(-(2p)/64)
// (rotation by -angle; executed reference's rotate_half = stack([x2, -x1]))
// ---------------------------------------------------------------------------
__global__ __launch_bounds__(256) void rope_inplace_neg() {
    const size_t idx = (size_t)blockIdx.x * 256 + threadIdx.x;   // pair index
    const int p  = (int)(idx & 31);
    const int s  = (int)((idx >> 5) & 2047);
    float* buf = (blockIdx.y == 0) ? g_q : g_k;
    size_t base = (idx >> 5) * HD + 2 * p;
    float inv_f = expf((float)(2 * p) * -0.14391156831212787f);
    float ang = (float)s * inv_f;
    float cs, sn;
    sincosf(ang, &cs, &sn);
    float2 x = *(float2*)(buf + base);
    float2 y;
    y.x = x.x * cs + x.y * sn;
    y.y = x.y * cs - x.x * sn;
    *(float2*)(buf + base) = y;
}

// ---------------------------------------------------------------------------
// Kernel 2: causal flash attention, fp32. 64x64 tiles, d=64. 256 thr (16x16).
// ---------------------------------------------------------------------------
#define PADW 68
#define ATTN_SMEM (4 * 64 * PADW * 4)

__global__ __launch_bounds__(256) void attn_flash() {
    extern __shared__ float sm[];
    float* Qs = sm;                 // [d][q]
    float* Ks = sm + 64*PADW;       // [d][k]
    float* Vs = sm + 2*64*PADW;     // [k][d]
    float* Ps = sm + 3*64*PADW;     // [k][q]

    const int tid = threadIdx.x;
    const int tx  = tid & 15;
    const int ty  = tid >> 4;
    const int bh  = blockIdx.y;
    const int qt  = blockIdx.x;
    const int q0  = qt * 64;
    const float* Q = g_q + (size_t)bh * SEQ * HD;
    const float* K = g_k + (size_t)bh * SEQ * HD;
    const float* V = g_v + (size_t)bh * SEQ * HD;

    for (int idx = tid; idx < 64*16; idx += 256) {
        int r = idx >> 4;
        int c = (idx & 15) << 2;
        float4 t = *(const float4*)(Q + (size_t)(q0 + r)*HD + c);
        Qs[(c+0)*PADW + r] = t.x;
        Qs[(c+1)*PADW + r] = t.y;
        Qs[(c+2)*PADW + r] = t.z;
        Qs[(c+3)*PADW + r] = t.w;
    }

    float mrow[4], lrow[4], O[4][4];
#pragma unroll
    for (int i = 0; i < 4; i++) {
        mrow[i] = -1e30f; lrow[i] = 0.f;
#pragma unroll
        for (int j = 0; j < 4; j++) O[i][j] = 0.f;
    }

    for (int kt = 0; kt <= qt; kt++) {
        const int k0 = kt * 64;
        __syncthreads();
        for (int idx = tid; idx < 64*16; idx += 256) {
            int r = idx >> 4;
            int c = (idx & 15) << 2;
            float4 t = *(const float4*)(K + (size_t)(k0 + r)*HD + c);
            Ks[(c+0)*PADW + r] = t.x;
            Ks[(c+1)*PADW + r] = t.y;
            Ks[(c+2)*PADW + r] = t.z;
            Ks[(c+3)*PADW + r] = t.w;
            float4 u = *(const float4*)(V + (size_t)(k0 + r)*HD + c);
            *(float4*)&Vs[r*PADW + c] = u;
        }
        __syncthreads();

        float s4[4][4];
#pragma unroll
        for (int i = 0; i < 4; i++)
#pragma unroll
            for (int j = 0; j < 4; j++) s4[i][j] = 0.f;

#pragma unroll 8
        for (int k = 0; k < 64; k++) {
            float4 a = *(const float4*)&Qs[k*PADW + ty*4];
            float4 b = *(const float4*)&Ks[k*PADW + tx*4];
            float av[4] = {a.x, a.y, a.z, a.w};
            float bv[4] = {b.x, b.y, b.z, b.w};
#pragma unroll
            for (int i = 0; i < 4; i++)
#pragma unroll
                for (int j = 0; j < 4; j++)
                    s4[i][j] = fmaf(av[i], bv[j], s4[i][j]);
        }

#pragma unroll
        for (int i = 0; i < 4; i++)
#pragma unroll
            for (int j = 0; j < 4; j++) {
                float sv = s4[i][j] * 0.125f;
                if (kt == qt && (k0 + tx*4 + j) > (q0 + ty*4 + i)) sv = -1e30f;
                s4[i][j] = sv;
            }

#pragma unroll
        for (int i = 0; i < 4; i++) {
            float tm = fmaxf(fmaxf(s4[i][0], s4[i][1]), fmaxf(s4[i][2], s4[i][3]));
#pragma unroll
            for (int off = 1; off < 16; off <<= 1)
                tm = fmaxf(tm, __shfl_xor_sync(0xffffffffu, tm, off));
            float mnew = fmaxf(mrow[i], tm);
            float fac  = __expf(mrow[i] - mnew);
            mrow[i] = mnew;
            float rs = 0.f;
#pragma unroll
            for (int j = 0; j < 4; j++) {
                float p = __expf(s4[i][j] - mnew);
                s4[i][j] = p;
                rs += p;
            }
#pragma unroll
            for (int off = 1; off < 16; off <<= 1)
                rs += __shfl_xor_sync(0xffffffffu, rs, off);
            lrow[i] = lrow[i] * fac + rs;
#pragma unroll
            for (int j = 0; j < 4; j++) O[i][j] *= fac;
        }

#pragma unroll
        for (int i = 0; i < 4; i++)
#pragma unroll
            for (int j = 0; j < 4; j++)
                Ps[(tx*4 + j)*PADW + (ty*4 + i)] = s4[i][j];
        __syncthreads();

#pragma unroll 8
        for (int k = 0; k < 64; k++) {
            float4 p = *(const float4*)&Ps[k*PADW + ty*4];
            float4 v = *(const float4*)&Vs[k*PADW + tx*4];
            float pv[4] = {p.x, p.y, p.z, p.w};
            float vv[4] = {v.x, v.y, v.z, v.w};
#pragma unroll
            for (int i = 0; i < 4; i++)
#pragma unroll
                for (int j = 0; j < 4; j++)
                    O[i][j] = fmaf(pv[i], vv[j], O[i][j]);
        }
    }

    const int b = bh >> 4;
    const int h = bh & 15;
#pragma unroll
    for (int i = 0; i < 4; i++) {
        float inv = 1.0f / lrow[i];
        int srow = q0 + ty*4 + i;
        float4 o = make_float4(O[i][0]*inv, O[i][1]*inv, O[i][2]*inv, O[i][3]*inv);
        *(float4*)&g_attn[((size_t)(b*SEQ + srow) * DM) + h*HD + tx*4] = o;
    }
}

// ---------------------------------------------------------------------------
// Kernel 3: output projection: OUT[m,e] = sum_d g_attn[m,d] * Wout[e,d]
// ---------------------------------------------------------------------------
__global__ __launch_bounds__(256) void out_gemm(const float* __restrict__ W,
                                                float* __restrict__ OUT) {
    __shared__ float As[8][128];
    __shared__ float Bs[8][128];
    const int tid = threadIdx.x;
    const int tx  = tid & 15;
    const int ty  = tid >> 4;
    const int m0  = blockIdx.y * 128;
    const int n0  = blockIdx.x * 128;
    const int lrow = tid >> 1;
    const int lk   = (tid & 1) << 2;
    const float* Ap = g_attn + (size_t)(m0 + lrow) * DM + lk;
    const float* Bp = W      + (size_t)(n0 + lrow) * DM + lk;

    float acc[8][8];
#pragma unroll
    for (int i = 0; i < 8; i++)
#pragma unroll
        for (int j = 0; j < 8; j++) acc[i][j] = 0.f;

    for (int kt = 0; kt < DM; kt += 8) {
        float4 a = *(const float4*)(Ap + kt);
        float4 b = *(const float4*)(Bp + kt);
        __syncthreads();
        As[lk+0][lrow] = a.x; As[lk+1][lrow] = a.y; As[lk+2][lrow] = a.z; As[lk+3][lrow] = a.w;
        Bs[lk+0][lrow] = b.x; Bs[lk+1][lrow] = b.y; Bs[lk+2][lrow] = b.z; Bs[lk+3][lrow] = b.w;
        __syncthreads();
#pragma unroll
        for (int k = 0; k < 8; k++) {
            float4 a0 = *(const float4*)&As[k][ty*8];
            float4 a1 = *(const float4*)&As[k][ty*8+4];
            float4 b0 = *(const float4*)&Bs[k][tx*8];
            float4 b1 = *(const float4*)&Bs[k][tx*8+4];
            float ar[8] = {a0.x,a0.y,a0.z,a0.w,a1.x,a1.y,a1.z,a1.w};
            float br[8] = {b0.x,b0.y,b0.z,b0.w,b1.x,b1.y,b1.z,b1.w};
#pragma unroll
            for (int i = 0; i < 8; i++)
#pragma unroll
                for (int j = 0; j < 8; j++)
                    acc[i][j] = fmaf(ar[i], br[j], acc[i][j]);
        }
    }

#pragma unroll
    for (int i = 0; i < 8; i++) {
        int m = m0 + ty*8 + i;
        float* op = OUT + (size_t)m * DM + n0 + tx*8;
        *(float4*)(op)     = make_float4(acc[i][0],acc[i][1],acc[i][2],acc[i][3]);
        *(float4*)(op + 4) = make_float4(acc[i][4],acc[i][5],acc[i][6],acc[i][7]);
    }
}

// ---------------------------------------------------------------------------
extern "C" void kernel_launch(void* const* d_in, const int* in_sizes, int n_in,
                              void* d_out, int out_size) {
    (void)out_size;
    const float* x = (const float*)d_in[0];
    const float* w_qkv = (const float*)d_in[1];
    const float* w_out = (const float*)d_in[2];
    for (int i = 0; i < n_in; i++) {
        if (in_sizes[i] == 8388608)      x     = (const float*)d_in[i];
        else if (in_sizes[i] == 3145728) w_qkv = (const float*)d_in[i];
        else if (in_sizes[i] == 1048576) w_out = (const float*)d_in[i];
    }
    float* out = (float*)d_out;

    cudaFuncSetAttribute(attn_flash, cudaFuncAttributeMaxDynamicSharedMemorySize,
                         ATTN_SMEM);

    qkv_gemm<<<dim3(3*DM/128, MTOT/128), 256>>>(x, w_qkv);
    rope_inplace_neg<<<dim3((BATCH*NH*SEQ*32)/256, 2), 256>>>();
    attn_flash<<<dim3(SEQ/64, BATCH*NH), 256, ATTN_SMEM>>>();
    out_gemm<<<dim3(DM/128, MTOT/128), 256>>>(w_out, out);
}

// round 8
// speedup vs baseline: 1.5700x; 1.5700x over previous
#include <cuda_runtime.h>
#include <cuda_bf16.h>
#include <math.h>
#include <stdint.h>

#define BATCH 4
#define SEQ   2048
#define DM    1024
#define NH    16
#define HD    64
#define MTOT  (BATCH*SEQ)   // 8192

// ---------------- scratch (__device__ statics; allocation-guard safe) -------
__device__ float g_q[(size_t)BATCH*NH*SEQ*HD];
__device__ float g_k[(size_t)BATCH*NH*SEQ*HD];
__device__ float g_v[(size_t)BATCH*NH*SEQ*HD];
__device__ float g_attn[(size_t)MTOT*DM];

__device__ __nv_bfloat16 s_xhi[(size_t)MTOT*DM];
__device__ __nv_bfloat16 s_xlo[(size_t)MTOT*DM];
__device__ __nv_bfloat16 s_whi[(size_t)3*DM*DM];
__device__ __nv_bfloat16 s_wlo[(size_t)3*DM*DM];
__device__ __nv_bfloat16 s_ohi[(size_t)DM*DM];
__device__ __nv_bfloat16 s_olo[(size_t)DM*DM];
__device__ __nv_bfloat16 s_ahi[(size_t)MTOT*DM];
__device__ __nv_bfloat16 s_alo[(size_t)MTOT*DM];

// ---------------- helpers ----------------------------------------------------
__device__ __forceinline__ uint32_t smem_u32(const void* p) {
    uint32_t a;
    asm("{ .reg .u64 t; cvta.to.shared.u64 t, %1; cvt.u32.u64 %0, t; }"
        : "=r"(a) : "l"(p));
    return a;
}
#define LDMX4(d, a) \
    asm volatile("ldmatrix.sync.aligned.m8n8.x4.shared.b16 {%0,%1,%2,%3}, [%4];" \
                 : "=r"((d)[0]), "=r"((d)[1]), "=r"((d)[2]), "=r"((d)[3]) : "r"(a))
#define MMA16816(c, a, b0, b1) \
    asm volatile("mma.sync.aligned.m16n8k16.row.col.f32.bf16.bf16.f32 " \
                 "{%0,%1,%2,%3}, {%4,%5,%6,%7}, {%8,%9}, {%0,%1,%2,%3};" \
                 : "+f"((c)[0]), "+f"((c)[1]), "+f"((c)[2]), "+f"((c)[3]) \
                 : "r"((a)[0]), "r"((a)[1]), "r"((a)[2]), "r"((a)[3]), \
                   "r"(b0), "r"(b1))

// ---------------------------------------------------------------------------
// fp32 -> bf16 hi/lo split
// ---------------------------------------------------------------------------
__global__ __launch_bounds__(256) void cvt_split(const float* __restrict__ src,
                                                 __nv_bfloat16* __restrict__ hi,
                                                 __nv_bfloat16* __restrict__ lo,
                                                 int n) {
    int i = blockIdx.x * 256 + threadIdx.x;
    if (i >= n) return;
    float x = src[i];
    __nv_bfloat16 h = __float2bfloat16(x);
    hi[i] = h;
    lo[i] = __float2bfloat16(x - __bfloat162float(h));
}

// ---------------------------------------------------------------------------
// Split-bf16 tensor-core GEMM via mma.sync (HMMA):
//   C[m,n] = sum_k A[m,k]*B[n,k]  (fp32-equivalent: hi*hi + hi*lo + lo*hi)
// CTA 128x128, 8 warps (2x4), warp tile 64x32. BK=32, cp.async double buffer.
// Smem chunk layout per buffer: [Ahi | Alo | Bhi | Blo], each 128 rows x 32
// bf16 (64B rows), 16B-unit swizzle: c16 ^= (row>>1)&3.
// mode 0: store OUT[m*DM+n]. mode 1: scatter to g_q/g_k/g_v head layout.
// ---------------------------------------------------------------------------
#define GEMM_SMEM 65536

__device__ __forceinline__ void stage_chunk(
    uint32_t smbase, int p, int c,
    const __nv_bfloat16* s0, const __nv_bfloat16* s1,
    const __nv_bfloat16* s2, const __nv_bfloat16* s3, int tid)
{
    const __nv_bfloat16* srcs[4] = {s0, s1, s2, s3};
    const uint32_t bufb = smbase + (uint32_t)p * 32768u;
#pragma unroll
    for (int comp = 0; comp < 4; comp++) {
        const __nv_bfloat16* s = srcs[comp] + c * 32;
        const uint32_t db = bufb + (uint32_t)comp * 8192u;
#pragma unroll
        for (int t = 0; t < 2; t++) {
            int idx = tid + t * 256;
            int row = idx >> 2, c16 = idx & 3;
            const void* gp = s + (size_t)row * DM + c16 * 8;
            uint32_t sw = db + (uint32_t)(row * 64)
                        + ((uint32_t)(c16 ^ ((row >> 1) & 3)) << 4);
            asm volatile("cp.async.cg.shared.global [%0], [%1], 16;"
                         :: "r"(sw), "l"(gp));
        }
    }
    asm volatile("cp.async.commit_group;" ::: "memory");
}

__device__ __forceinline__ float* qkv_ptr(int m, int col) {
    int which = col >> 10, h = (col & 1023) >> 6, dd = col & 63;
    float* dst = (which == 0) ? g_q : (which == 1) ? g_k : g_v;
    int b = m >> 11, s = m & 2047;
    return dst + (((size_t)(b * NH + h) * SEQ + s) * HD) + dd;
}

__global__ __launch_bounds__(256) void gemm_mma(
    const __nv_bfloat16* __restrict__ Ahi, const __nv_bfloat16* __restrict__ Alo,
    const __nv_bfloat16* __restrict__ Bhi, const __nv_bfloat16* __restrict__ Blo,
    float* __restrict__ OUT, int mode)
{
    extern __shared__ __align__(128) char smraw[];
    const uint32_t smbase = smem_u32(smraw);
    const int tid  = threadIdx.x;
    const int wid  = tid >> 5;
    const int lane = tid & 31;
    const int wm   = wid >> 2;          // 0..1
    const int wn   = wid & 3;           // 0..3
    const int n0   = blockIdx.x * 128;
    const int m0   = blockIdx.y * 128;

    const __nv_bfloat16* gAhi = Ahi + (size_t)m0 * DM;
    const __nv_bfloat16* gAlo = Alo + (size_t)m0 * DM;
    const __nv_bfloat16* gBhi = Bhi + (size_t)n0 * DM;
    const __nv_bfloat16* gBlo = Blo + (size_t)n0 * DM;

    float C[4][4][4];
#pragma unroll
    for (int i = 0; i < 4; i++)
#pragma unroll
        for (int j = 0; j < 4; j++)
#pragma unroll
            for (int k = 0; k < 4; k++) C[i][j][k] = 0.f;

    const int g = lane >> 3, r = lane & 7;

    stage_chunk(smbase, 0, 0, gAhi, gAlo, gBhi, gBlo, tid);

    for (int c = 0; c < 32; c++) {
        const int p = c & 1;
        if (c < 31) {
            stage_chunk(smbase, p ^ 1, c + 1, gAhi, gAlo, gBhi, gBlo, tid);
            asm volatile("cp.async.wait_group 1;" ::: "memory");
        } else {
            asm volatile("cp.async.wait_group 0;" ::: "memory");
        }
        __syncthreads();

        const uint32_t ab = smbase + (uint32_t)p * 32768u;
#pragma unroll
        for (int kh = 0; kh < 2; kh++) {
            const int kkc = kh * 2;     // c16 base (k16 half)
            uint32_t ahi[4][4], alo[4][4];
#pragma unroll
            for (int mf = 0; mf < 4; mf++) {
                int row = wm * 64 + mf * 16 + (g & 1) * 8 + r;
                int c16 = kkc + (g >> 1);
                uint32_t sw = (uint32_t)(row * 64)
                            + ((uint32_t)(c16 ^ ((row >> 1) & 3)) << 4);
                LDMX4(ahi[mf], ab + sw);
                LDMX4(alo[mf], ab + 8192u + sw);
            }
            uint32_t bhi[4][2], blo[4][2];
#pragma unroll
            for (int bp = 0; bp < 2; bp++) {
                int row = wn * 32 + bp * 16 + (g >> 1) * 8 + r;
                int c16 = kkc + (g & 1);
                uint32_t sw = (uint32_t)(row * 64)
                            + ((uint32_t)(c16 ^ ((row >> 1) & 3)) << 4);
                uint32_t t[4];
                LDMX4(t, ab + 16384u + sw);
                bhi[bp*2][0] = t[0]; bhi[bp*2][1] = t[1];
                bhi[bp*2+1][0] = t[2]; bhi[bp*2+1][1] = t[3];
                LDMX4(t, ab + 24576u + sw);
                blo[bp*2][0] = t[0]; blo[bp*2][1] = t[1];
                blo[bp*2+1][0] = t[2]; blo[bp*2+1][1] = t[3];
            }
#pragma unroll
            for (int mf = 0; mf < 4; mf++)
#pragma unroll
                for (int nf = 0; nf < 4; nf++) {
                    MMA16816(C[mf][nf], ahi[mf], bhi[nf][0], bhi[nf][1]);
                    MMA16816(C[mf][nf], ahi[mf], blo[nf][0], blo[nf][1]);
                    MMA16816(C[mf][nf], alo[mf], bhi[nf][0], bhi[nf][1]);
                }
        }
        __syncthreads();
    }

    // Epilogue
#pragma unroll
    for (int mf = 0; mf < 4; mf++) {
#pragma unroll
        for (int nf = 0; nf < 4; nf++) {
            int row0 = m0 + wm * 64 + mf * 16 + (lane >> 2);
            int col  = n0 + wn * 32 + nf * 8 + (lane & 3) * 2;
            float2 v0 = make_float2(C[mf][nf][0], C[mf][nf][1]);
            float2 v1 = make_float2(C[mf][nf][2], C[mf][nf][3]);
            if (mode == 0) {
                *(float2*)(OUT + (size_t)row0 * DM + col) = v0;
                *(float2*)(OUT + (size_t)(row0 + 8) * DM + col) = v1;
            } else {
                *(float2*)qkv_ptr(row0, col) = v0;
                *(float2*)qkv_ptr(row0 + 8, col) = v1;
            }
        }
    }
}

// ---------------------------------------------------------------------------
// RoPE in place (negated-sin interleaved — validated r6)
// ---------------------------------------------------------------------------
__global__ __launch_bounds__(256) void rope_inplace_neg() {
    const size_t idx = (size_t)blockIdx.x * 256 + threadIdx.x;
    const int p  = (int)(idx & 31);
    const int s  = (int)((idx >> 5) & 2047);
    float* buf = (blockIdx.y == 0) ? g_q : g_k;
    size_t base = (idx >> 5) * HD + 2 * p;
    float inv_f = expf((float)(2 * p) * -0.14391156831212787f);
    float ang = (float)s * inv_f;
    float cs, sn;
    sincosf(ang, &cs, &sn);
    float2 x = *(float2*)(buf + base);
    float2 y;
    y.x = x.x * cs + x.y * sn;
    y.y = x.y * cs - x.x * sn;
    *(float2*)(buf + base) = y;
}

// ---------------------------------------------------------------------------
// Flash attention fp32 (unchanged from passing r6)
// ---------------------------------------------------------------------------
#define PADW 68
#define ATTN_SMEM (4 * 64 * PADW * 4)

__global__ __launch_bounds__(256) void attn_flash() {
    extern __shared__ float sm[];
    float* Qs = sm;
    float* Ks = sm + 64*PADW;
    float* Vs = sm + 2*64*PADW;
    float* Ps = sm + 3*64*PADW;

    const int tid = threadIdx.x;
    const int tx  = tid & 15;
    const int ty  = tid >> 4;
    const int bh  = blockIdx.y;
    const int qt  = blockIdx.x;
    const int q0  = qt * 64;
    const float* Q = g_q + (size_t)bh * SEQ * HD;
    const float* K = g_k + (size_t)bh * SEQ * HD;
    const float* V = g_v + (size_t)bh * SEQ * HD;

    for (int idx = tid; idx < 64*16; idx += 256) {
        int r = idx >> 4;
        int c = (idx & 15) << 2;
        float4 t = *(const float4*)(Q + (size_t)(q0 + r)*HD + c);
        Qs[(c+0)*PADW + r] = t.x;
        Qs[(c+1)*PADW + r] = t.y;
        Qs[(c+2)*PADW + r] = t.z;
        Qs[(c+3)*PADW + r] = t.w;
    }

    float mrow[4], lrow[4], O[4][4];
#pragma unroll
    for (int i = 0; i < 4; i++) {
        mrow[i] = -1e30f; lrow[i] = 0.f;
#pragma unroll
        for (int j = 0; j < 4; j++) O[i][j] = 0.f;
    }

    for (int kt = 0; kt <= qt; kt++) {
        const int k0 = kt * 64;
        __syncthreads();
        for (int idx = tid; idx < 64*16; idx += 256) {
            int r = idx >> 4;
            int c = (idx & 15) << 2;
            float4 t = *(const float4*)(K + (size_t)(k0 + r)*HD + c);
            Ks[(c+0)*PADW + r] = t.x;
            Ks[(c+1)*PADW + r] = t.y;
            Ks[(c+2)*PADW + r] = t.z;
            Ks[(c+3)*PADW + r] = t.w;
            float4 u = *(const float4*)(V + (size_t)(k0 + r)*HD + c);
            *(float4*)&Vs[r*PADW + c] = u;
        }
        __syncthreads();

        float s4[4][4];
#pragma unroll
        for (int i = 0; i < 4; i++)
#pragma unroll
            for (int j = 0; j < 4; j++) s4[i][j] = 0.f;

#pragma unroll 8
        for (int k = 0; k < 64; k++) {
            float4 a = *(const float4*)&Qs[k*PADW + ty*4];
            float4 b = *(const float4*)&Ks[k*PADW + tx*4];
            float av[4] = {a.x, a.y, a.z, a.w};
            float bv[4] = {b.x, b.y, b.z, b.w};
#pragma unroll
            for (int i = 0; i < 4; i++)
#pragma unroll
                for (int j = 0; j < 4; j++)
                    s4[i][j] = fmaf(av[i], bv[j], s4[i][j]);
        }

#pragma unroll
        for (int i = 0; i < 4; i++)
#pragma unroll
            for (int j = 0; j < 4; j++) {
                float sv = s4[i][j] * 0.125f;
                if (kt == qt && (k0 + tx*4 + j) > (q0 + ty*4 + i)) sv = -1e30f;
                s4[i][j] = sv;
            }

#pragma unroll
        for (int i = 0; i < 4; i++) {
            float tm = fmaxf(fmaxf(s4[i][0], s4[i][1]), fmaxf(s4[i][2], s4[i][3]));
#pragma unroll
            for (int off = 1; off < 16; off <<= 1)
                tm = fmaxf(tm, __shfl_xor_sync(0xffffffffu, tm, off));
            float mnew = fmaxf(mrow[i], tm);
            float fac  = __expf(mrow[i] - mnew);
            mrow[i] = mnew;
            float rs = 0.f;
#pragma unroll
            for (int j = 0; j < 4; j++) {
                float p = __expf(s4[i][j] - mnew);
                s4[i][j] = p;
                rs += p;
            }
#pragma unroll
            for (int off = 1; off < 16; off <<= 1)
                rs += __shfl_xor_sync(0xffffffffu, rs, off);
            lrow[i] = lrow[i] * fac + rs;
#pragma unroll
            for (int j = 0; j < 4; j++) O[i][j] *= fac;
        }

#pragma unroll
        for (int i = 0; i < 4; i++)
#pragma unroll
            for (int j = 0; j < 4; j++)
                Ps[(tx*4 + j)*PADW + (ty*4 + i)] = s4[i][j];
        __syncthreads();

#pragma unroll 8
        for (int k = 0; k < 64; k++) {
            float4 p = *(const float4*)&Ps[k*PADW + ty*4];
            float4 v = *(const float4*)&Vs[k*PADW + tx*4];
            float pv[4] = {p.x, p.y, p.z, p.w};
            float vv[4] = {v.x, v.y, v.z, v.w};
#pragma unroll
            for (int i = 0; i < 4; i++)
#pragma unroll
                for (int j = 0; j < 4; j++)
                    O[i][j] = fmaf(pv[i], vv[j], O[i][j]);
        }
    }

    const int b = bh >> 4;
    const int h = bh & 15;
#pragma unroll
    for (int i = 0; i < 4; i++) {
        float inv = 1.0f / lrow[i];
        int srow = q0 + ty*4 + i;
        float4 o = make_float4(O[i][0]*inv, O[i][1]*inv, O[i][2]*inv, O[i][3]*inv);
        *(float4*)&g_attn[((size_t)(b*SEQ + srow) * DM) + h*HD + tx*4] = o;
    }
}

// ---------------------------------------------------------------------------
extern "C" void kernel_launch(void* const* d_in, const int* in_sizes, int n_in,
                              void* d_out, int out_size) {
    (void)out_size;
    const float* x = (const float*)d_in[0];
    const float* w_qkv = (const float*)d_in[1];
    const float* w_out = (const float*)d_in[2];
    for (int i = 0; i < n_in; i++) {
        if (in_sizes[i] == 8388608)      x     = (const float*)d_in[i];
        else if (in_sizes[i] == 3145728) w_qkv = (const float*)d_in[i];
        else if (in_sizes[i] == 1048576) w_out = (const float*)d_in[i];
    }
    float* out = (float*)d_out;

    void *p_xhi, *p_xlo, *p_whi, *p_wlo, *p_ohi, *p_olo, *p_ahi, *p_alo, *p_attn;
    cudaGetSymbolAddress(&p_xhi, s_xhi);
    cudaGetSymbolAddress(&p_xlo, s_xlo);
    cudaGetSymbolAddress(&p_whi, s_whi);
    cudaGetSymbolAddress(&p_wlo, s_wlo);
    cudaGetSymbolAddress(&p_ohi, s_ohi);
    cudaGetSymbolAddress(&p_olo, s_olo);
    cudaGetSymbolAddress(&p_ahi, s_ahi);
    cudaGetSymbolAddress(&p_alo, s_alo);
    cudaGetSymbolAddress(&p_attn, g_attn);

    cudaFuncSetAttribute(gemm_mma, cudaFuncAttributeMaxDynamicSharedMemorySize, GEMM_SMEM);
    cudaFuncSetAttribute(attn_flash, cudaFuncAttributeMaxDynamicSharedMemorySize, ATTN_SMEM);

    cvt_split<<<(MTOT*DM)/256, 256>>>(x, (__nv_bfloat16*)p_xhi, (__nv_bfloat16*)p_xlo, MTOT*DM);
    cvt_split<<<(3*DM*DM)/256, 256>>>(w_qkv, (__nv_bfloat16*)p_whi, (__nv_bfloat16*)p_wlo, 3*DM*DM);
    cvt_split<<<(DM*DM)/256, 256>>>(w_out, (__nv_bfloat16*)p_ohi, (__nv_bfloat16*)p_olo, DM*DM);

    gemm_mma<<<dim3(3*DM/128, MTOT/128), 256, GEMM_SMEM>>>(
        (const __nv_bfloat16*)p_xhi, (const __nv_bfloat16*)p_xlo,
        (const __nv_bfloat16*)p_whi, (const __nv_bfloat16*)p_wlo, nullptr, 1);

    rope_inplace_neg<<<dim3((BATCH*NH*SEQ*32)/256, 2), 256>>>();
    attn_flash<<<dim3(SEQ/64, BATCH*NH), 256, ATTN_SMEM>>>();

    cvt_split<<<(MTOT*DM)/256, 256>>>((const float*)p_attn,
        (__nv_bfloat16*)p_ahi, (__nv_bfloat16*)p_alo, MTOT*DM);

    gemm_mma<<<dim3(DM/128, MTOT/128), 256, GEMM_SMEM>>>(
        (const __nv_bfloat16*)p_ahi, (const __nv_bfloat16*)p_alo,
        (const __nv_bfloat16*)p_ohi, (const __nv_bfloat16*)p_olo, out, 0);
}

// round 9
// speedup vs baseline: 2.9480x; 1.8777x over previous
#include <cuda_runtime.h>
#include <cuda_bf16.h>
#include <math.h>
#include <stdint.h>

#define BATCH 4
#define SEQ   2048
#define DM    1024
#define NH    16
#define HD    64
#define MTOT  (BATCH*SEQ)   // 8192

// ---------------- scratch (__device__ statics; allocation-guard safe) -------
__device__ float g_q[(size_t)BATCH*NH*SEQ*HD];
__device__ float g_k[(size_t)BATCH*NH*SEQ*HD];
__device__ float g_v[(size_t)BATCH*NH*SEQ*HD];

__device__ __nv_bfloat16 s_xhi[(size_t)MTOT*DM];
__device__ __nv_bfloat16 s_xlo[(size_t)MTOT*DM];
__device__ __nv_bfloat16 s_whi[(size_t)3*DM*DM];
__device__ __nv_bfloat16 s_wlo[(size_t)3*DM*DM];
__device__ __nv_bfloat16 s_ohi[(size_t)DM*DM];
__device__ __nv_bfloat16 s_olo[(size_t)DM*DM];
__device__ __nv_bfloat16 s_ahi[(size_t)MTOT*DM];
__device__ __nv_bfloat16 s_alo[(size_t)MTOT*DM];

__device__ __nv_bfloat16 s_qhi[(size_t)BATCH*NH*SEQ*HD];
__device__ __nv_bfloat16 s_qlo[(size_t)BATCH*NH*SEQ*HD];
__device__ __nv_bfloat16 s_khi[(size_t)BATCH*NH*SEQ*HD];
__device__ __nv_bfloat16 s_klo[(size_t)BATCH*NH*SEQ*HD];
__device__ __nv_bfloat16 s_vthi[(size_t)BATCH*NH*HD*SEQ];  // [bh][d][s]
__device__ __nv_bfloat16 s_vtlo[(size_t)BATCH*NH*HD*SEQ];

// ---------------- helpers ----------------------------------------------------
__device__ __forceinline__ uint32_t smem_u32(const void* p) {
    uint32_t a;
    asm("{ .reg .u64 t; cvta.to.shared.u64 t, %1; cvt.u32.u64 %0, t; }"
        : "=r"(a) : "l"(p));
    return a;
}
#define LDMX4(d, a) \
    asm volatile("ldmatrix.sync.aligned.m8n8.x4.shared.b16 {%0,%1,%2,%3}, [%4];" \
                 : "=r"((d)[0]), "=r"((d)[1]), "=r"((d)[2]), "=r"((d)[3]) : "r"(a))
#define MMA16816(c, a, b0, b1) \
    asm volatile("mma.sync.aligned.m16n8k16.row.col.f32.bf16.bf16.f32 " \
                 "{%0,%1,%2,%3}, {%4,%5,%6,%7}, {%8,%9}, {%0,%1,%2,%3};" \
                 : "+f"((c)[0]), "+f"((c)[1]), "+f"((c)[2]), "+f"((c)[3]) \
                 : "r"((a)[0]), "r"((a)[1]), "r"((a)[2]), "r"((a)[3]), \
                   "r"(b0), "r"(b1))
#define CPASYNC16(sa, gp) \
    asm volatile("cp.async.cg.shared.global [%0], [%1], 16;" :: "r"(sa), "l"(gp))

__device__ __forceinline__ uint32_t pack_bf2(float a, float b) {
    __nv_bfloat162 t;
    t.x = __float2bfloat16(a);
    t.y = __float2bfloat16(b);
    return *reinterpret_cast<uint32_t*>(&t);
}
__device__ __forceinline__ void split2(float a, float b, uint32_t& hi, uint32_t& lo) {
    __nv_bfloat16 ah = __float2bfloat16(a), bh = __float2bfloat16(b);
    __nv_bfloat162 h; h.x = ah; h.y = bh;
    hi = *reinterpret_cast<uint32_t*>(&h);
    lo = pack_bf2(a - __bfloat162float(ah), b - __bfloat162float(bh));
}

// ---------------------------------------------------------------------------
// fp32 -> bf16 hi/lo split (inputs)
// ---------------------------------------------------------------------------
__global__ __launch_bounds__(256) void cvt_split(const float* __restrict__ src,
                                                 __nv_bfloat16* __restrict__ hi,
                                                 __nv_bfloat16* __restrict__ lo,
                                                 int n) {
    int i = blockIdx.x * 256 + threadIdx.x;
    if (i >= n) return;
    float x = src[i];
    __nv_bfloat16 h = __float2bfloat16(x);
    hi[i] = h;
    lo[i] = __float2bfloat16(x - __bfloat162float(h));
}

// ---------------------------------------------------------------------------
// Split-bf16 tensor-core GEMM (verified r8). mode 0: OUT; mode 1: qkv scatter.
// ---------------------------------------------------------------------------
#define GEMM_SMEM 65536

__device__ __forceinline__ void stage_chunk(
    uint32_t smbase, int p, int c,
    const __nv_bfloat16* s0, const __nv_bfloat16* s1,
    const __nv_bfloat16* s2, const __nv_bfloat16* s3, int tid)
{
    const __nv_bfloat16* srcs[4] = {s0, s1, s2, s3};
    const uint32_t bufb = smbase + (uint32_t)p * 32768u;
#pragma unroll
    for (int comp = 0; comp < 4; comp++) {
        const __nv_bfloat16* s = srcs[comp] + c * 32;
        const uint32_t db = bufb + (uint32_t)comp * 8192u;
#pragma unroll
        for (int t = 0; t < 2; t++) {
            int idx = tid + t * 256;
            int row = idx >> 2, c16 = idx & 3;
            const void* gp = s + (size_t)row * DM + c16 * 8;
            uint32_t sw = db + (uint32_t)(row * 64)
                        + ((uint32_t)(c16 ^ ((row >> 1) & 3)) << 4);
            CPASYNC16(sw, gp);
        }
    }
    asm volatile("cp.async.commit_group;" ::: "memory");
}

__device__ __forceinline__ float* qkv_ptr(int m, int col) {
    int which = col >> 10, h = (col & 1023) >> 6, dd = col & 63;
    float* dst = (which == 0) ? g_q : (which == 1) ? g_k : g_v;
    int b = m >> 11, s = m & 2047;
    return dst + (((size_t)(b * NH + h) * SEQ + s) * HD) + dd;
}

__global__ __launch_bounds__(256) void gemm_mma(
    const __nv_bfloat16* __restrict__ Ahi, const __nv_bfloat16* __restrict__ Alo,
    const __nv_bfloat16* __restrict__ Bhi, const __nv_bfloat16* __restrict__ Blo,
    float* __restrict__ OUT, int mode)
{
    extern __shared__ __align__(128) char smraw[];
    const uint32_t smbase = smem_u32(smraw);
    const int tid  = threadIdx.x;
    const int wid  = tid >> 5;
    const int lane = tid & 31;
    const int wm   = wid >> 2;
    const int wn   = wid & 3;
    const int n0   = blockIdx.x * 128;
    const int m0   = blockIdx.y * 128;

    const __nv_bfloat16* gAhi = Ahi + (size_t)m0 * DM;
    const __nv_bfloat16* gAlo = Alo + (size_t)m0 * DM;
    const __nv_bfloat16* gBhi = Bhi + (size_t)n0 * DM;
    const __nv_bfloat16* gBlo = Blo + (size_t)n0 * DM;

    float C[4][4][4];
#pragma unroll
    for (int i = 0; i < 4; i++)
#pragma unroll
        for (int j = 0; j < 4; j++)
#pragma unroll
            for (int k = 0; k < 4; k++) C[i][j][k] = 0.f;

    const int g = lane >> 3, r = lane & 7;

    stage_chunk(smbase, 0, 0, gAhi, gAlo, gBhi, gBlo, tid);

    for (int c = 0; c < 32; c++) {
        const int p = c & 1;
        if (c < 31) {
            stage_chunk(smbase, p ^ 1, c + 1, gAhi, gAlo, gBhi, gBlo, tid);
            asm volatile("cp.async.wait_group 1;" ::: "memory");
        } else {
            asm volatile("cp.async.wait_group 0;" ::: "memory");
        }
        __syncthreads();

        const uint32_t ab = smbase + (uint32_t)p * 32768u;
#pragma unroll
        for (int kh = 0; kh < 2; kh++) {
            const int kkc = kh * 2;
            uint32_t ahi[4][4], alo[4][4];
#pragma unroll
            for (int mf = 0; mf < 4; mf++) {
                int row = wm * 64 + mf * 16 + (g & 1) * 8 + r;
                int c16 = kkc + (g >> 1);
                uint32_t sw = (uint32_t)(row * 64)
                            + ((uint32_t)(c16 ^ ((row >> 1) & 3)) << 4);
                LDMX4(ahi[mf], ab + sw);
                LDMX4(alo[mf], ab + 8192u + sw);
            }
            uint32_t bhi[4][2], blo[4][2];
#pragma unroll
            for (int bp = 0; bp < 2; bp++) {
                int row = wn * 32 + bp * 16 + (g >> 1) * 8 + r;
                int c16 = kkc + (g & 1);
                uint32_t sw = (uint32_t)(row * 64)
                            + ((uint32_t)(c16 ^ ((row >> 1) & 3)) << 4);
                uint32_t t[4];
                LDMX4(t, ab + 16384u + sw);
                bhi[bp*2][0] = t[0]; bhi[bp*2][1] = t[1];
                bhi[bp*2+1][0] = t[2]; bhi[bp*2+1][1] = t[3];
                LDMX4(t, ab + 24576u + sw);
                blo[bp*2][0] = t[0]; blo[bp*2][1] = t[1];
                blo[bp*2+1][0] = t[2]; blo[bp*2+1][1] = t[3];
            }
#pragma unroll
            for (int mf = 0; mf < 4; mf++)
#pragma unroll
                for (int nf = 0; nf < 4; nf++) {
                    MMA16816(C[mf][nf], ahi[mf], bhi[nf][0], bhi[nf][1]);
                    MMA16816(C[mf][nf], ahi[mf], blo[nf][0], blo[nf][1]);
                    MMA16816(C[mf][nf], alo[mf], bhi[nf][0], bhi[nf][1]);
                }
        }
        __syncthreads();
    }

#pragma unroll
    for (int mf = 0; mf < 4; mf++) {
#pragma unroll
        for (int nf = 0; nf < 4; nf++) {
            int row0 = m0 + wm * 64 + mf * 16 + (lane >> 2);
            int col  = n0 + wn * 32 + nf * 8 + (lane & 3) * 2;
            float2 v0 = make_float2(C[mf][nf][0], C[mf][nf][1]);
            float2 v1 = make_float2(C[mf][nf][2], C[mf][nf][3]);
            if (mode == 0) {
                *(float2*)(OUT + (size_t)row0 * DM + col) = v0;
                *(float2*)(OUT + (size_t)(row0 + 8) * DM + col) = v1;
            } else {
                *(float2*)qkv_ptr(row0, col) = v0;
                *(float2*)qkv_ptr(row0 + 8, col) = v1;
            }
        }
    }
}

// ---------------------------------------------------------------------------
// RoPE (neg-sin interleaved, validated) + split to bf16 hi/lo
// ---------------------------------------------------------------------------
__global__ __launch_bounds__(256) void rope_split() {
    const size_t idx = (size_t)blockIdx.x * 256 + threadIdx.x;
    const int p  = (int)(idx & 31);
    const int s  = (int)((idx >> 5) & 2047);
    const float* src = (blockIdx.y == 0) ? g_q : g_k;
    __nv_bfloat16* dhi = (blockIdx.y == 0) ? s_qhi : s_khi;
    __nv_bfloat16* dlo = (blockIdx.y == 0) ? s_qlo : s_klo;
    size_t base = (idx >> 5) * HD + 2 * p;
    float inv_f = expf((float)(2 * p) * -0.14391156831212787f);
    float ang = (float)s * inv_f;
    float cs, sn;
    sincosf(ang, &cs, &sn);
    float2 x = *(const float2*)(src + base);
    float y0 = x.x * cs + x.y * sn;
    float y1 = x.y * cs - x.x * sn;
    uint32_t hi, lo;
    split2(y0, y1, hi, lo);
    *(uint32_t*)(dhi + base) = hi;
    *(uint32_t*)(dlo + base) = lo;
}

// ---------------------------------------------------------------------------
// V transpose + split: g_v fp32 [bh][s][d] -> s_vthi/s_vtlo [bh][d][s]
// grid (64 bh, 32 s-tiles), 256 threads, 64x64 tile
// ---------------------------------------------------------------------------
__global__ __launch_bounds__(256) void transpose_v() {
    __shared__ float t[64][65];
    const int bh = blockIdx.x, s0 = blockIdx.y * 64;
    const int tid = threadIdx.x;
    const float* src = g_v + (size_t)bh * SEQ * HD + (size_t)s0 * HD;
#pragma unroll
    for (int i = 0; i < 4; i++) {
        int idx = tid + i * 256;               // float4 index over 64x16
        int rr = idx >> 4, cc = (idx & 15) << 2;
        float4 v = *(const float4*)(src + rr * HD + cc);
        t[rr][cc] = v.x; t[rr][cc+1] = v.y; t[rr][cc+2] = v.z; t[rr][cc+3] = v.w;
    }
    __syncthreads();
    __nv_bfloat16* dhi = s_vthi + (size_t)bh * HD * SEQ + s0;
    __nv_bfloat16* dlo = s_vtlo + (size_t)bh * HD * SEQ + s0;
#pragma unroll
    for (int i = 0; i < 8; i++) {
        int idx = tid + i * 256;               // pair index over 64d x 32pairs
        int d = idx >> 5, sp = (idx & 31) << 1;
        uint32_t hi, lo;
        split2(t[sp][d], t[sp+1][d], hi, lo);
        *(uint32_t*)(dhi + (size_t)d * SEQ + sp) = hi;
        *(uint32_t*)(dlo + (size_t)d * SEQ + sp) = lo;
    }
}

// ---------------------------------------------------------------------------
// Flash attention, split-bf16 mma.sync.
// CTA: (bh, qt) -> 128 q-rows; 8 warps x 16 rows. K-tiles of 64.
// Smem: Qhi[16K] Qlo[16K] | stage p in {0,1}: Khi 8K, Klo 8K, Vhi 8K, Vlo 8K.
// All tiles 64 cols bf16 = 128B rows; swizzle c16 ^= row&7.
// ---------------------------------------------------------------------------
#define AT_SMEM (32768 + 2*32768)

__device__ __forceinline__ void at_stage64(uint32_t dst, const __nv_bfloat16* src,
                                           int rowstride, int tid) {
#pragma unroll
    for (int t = 0; t < 2; t++) {
        int idx = tid + t * 256;
        int row = idx >> 3, c16 = idx & 7;
        const void* gp = src + (size_t)row * rowstride + c16 * 8;
        uint32_t sa = dst + (uint32_t)(row * 128 + ((c16 ^ (row & 7)) << 4));
        CPASYNC16(sa, gp);
    }
}

__global__ __launch_bounds__(256) void attn_mma() {
    extern __shared__ __align__(128) char smraw[];
    const uint32_t sb = smem_u32(smraw);
    const int tid = threadIdx.x;
    const int wid = tid >> 5;
    const int lane = tid & 31;
    const int bh = blockIdx.x;
    const int qt = 15 - blockIdx.y;           // heavy tiles first
    const int q0 = qt * 128;
    const int nkt = 2 * qt + 2;

    const size_t qk_off = (size_t)bh * SEQ * HD;
    const size_t vt_off = (size_t)bh * HD * SEQ;

    // stage Q (128 rows x 64)
#pragma unroll
    for (int t = 0; t < 4; t++) {
        int idx = tid + t * 256;
        int row = idx >> 3, c16 = idx & 7;
        uint32_t sw = (uint32_t)(row * 128 + ((c16 ^ (row & 7)) << 4));
        CPASYNC16(sb + sw, s_qhi + qk_off + (size_t)(q0 + row) * HD + c16 * 8);
        CPASYNC16(sb + 16384u + sw, s_qlo + qk_off + (size_t)(q0 + row) * HD + c16 * 8);
    }
    // stage KV tile 0
    {
        uint32_t d0 = sb + 32768u;
        at_stage64(d0,           s_khi + qk_off, HD, tid);
        at_stage64(d0 + 8192u,   s_klo + qk_off, HD, tid);
        at_stage64(d0 + 16384u,  s_vthi + vt_off, SEQ, tid);
        at_stage64(d0 + 24576u,  s_vtlo + vt_off, SEQ, tid);
    }
    asm volatile("cp.async.commit_group;" ::: "memory");

    float O[8][4];
#pragma unroll
    for (int nf = 0; nf < 8; nf++)
#pragma unroll
        for (int j = 0; j < 4; j++) O[nf][j] = 0.f;
    float m0 = -1e30f, m1 = -1e30f, l0 = 0.f, l1 = 0.f;

    const int r0g = q0 + wid * 16 + (lane >> 2);
    const int arow = wid * 16 + ((lane >> 3) & 1) * 8 + (lane & 7);
    const int brow_b = (lane & 7) + (lane >> 4) * 8;
    const int bsel = (lane >> 3) & 1;
    const int asel = lane >> 4;

    for (int kt = 0; kt < nkt; kt++) {
        const int p = kt & 1;
        const int k0 = kt * 64;
        asm volatile("cp.async.wait_group 0;" ::: "memory");
        __syncthreads();
        if (kt + 1 < nkt) {
            uint32_t dn = sb + 32768u + (uint32_t)(p ^ 1) * 32768u;
            int kn = (kt + 1) * 64;
            at_stage64(dn,          s_khi + qk_off + (size_t)kn * HD, HD, tid);
            at_stage64(dn + 8192u,  s_klo + qk_off + (size_t)kn * HD, HD, tid);
            at_stage64(dn + 16384u, s_vthi + vt_off + kn, SEQ, tid);
            at_stage64(dn + 24576u, s_vtlo + vt_off + kn, SEQ, tid);
            asm volatile("cp.async.commit_group;" ::: "memory");
        }
        const uint32_t kb = sb + 32768u + (uint32_t)p * 32768u;

        // ---- S = Q.K^T (3-product split) ----
        float S[8][4];
#pragma unroll
        for (int nf = 0; nf < 8; nf++)
#pragma unroll
            for (int j = 0; j < 4; j++) S[nf][j] = 0.f;
#pragma unroll
        for (int kh = 0; kh < 4; kh++) {
            int ac16 = 2 * kh + asel;
            uint32_t aoff = (uint32_t)(arow * 128 + ((ac16 ^ (arow & 7)) << 4));
            uint32_t qh[4], ql[4];
            LDMX4(qh, sb + aoff);
            LDMX4(ql, sb + 16384u + aoff);
            int bc16 = 2 * kh + bsel;
#pragma unroll
            for (int bp = 0; bp < 4; bp++) {
                int brow = bp * 16 + brow_b;
                uint32_t boff = (uint32_t)(brow * 128 + ((bc16 ^ (brow & 7)) << 4));
                uint32_t th[4], tl[4];
                LDMX4(th, kb + boff);
                LDMX4(tl, kb + 8192u + boff);
                MMA16816(S[2*bp],   qh, th[0], th[1]);
                MMA16816(S[2*bp],   qh, tl[0], tl[1]);
                MMA16816(S[2*bp],   ql, th[0], th[1]);
                MMA16816(S[2*bp+1], qh, th[2], th[3]);
                MMA16816(S[2*bp+1], qh, tl[2], tl[3]);
                MMA16816(S[2*bp+1], ql, th[2], th[3]);
            }
        }

        // ---- scale + causal mask ----
        const bool msk = (k0 >= q0);
#pragma unroll
        for (int nf = 0; nf < 8; nf++)
#pragma unroll
            for (int j = 0; j < 4; j++) {
                float sv = S[nf][j] * 0.125f;
                if (msk) {
                    int col = k0 + nf * 8 + (lane & 3) * 2 + (j & 1);
                    int row = (j < 2) ? r0g : r0g + 8;
                    if (col > row) sv = -1e30f;
                }
                S[nf][j] = sv;
            }

        // ---- online softmax ----
        float tm0 = -1e30f, tm1 = -1e30f;
#pragma unroll
        for (int nf = 0; nf < 8; nf++) {
            tm0 = fmaxf(tm0, fmaxf(S[nf][0], S[nf][1]));
            tm1 = fmaxf(tm1, fmaxf(S[nf][2], S[nf][3]));
        }
        tm0 = fmaxf(tm0, __shfl_xor_sync(0xffffffffu, tm0, 1));
        tm0 = fmaxf(tm0, __shfl_xor_sync(0xffffffffu, tm0, 2));
        tm1 = fmaxf(tm1, __shfl_xor_sync(0xffffffffu, tm1, 1));
        tm1 = fmaxf(tm1, __shfl_xor_sync(0xffffffffu, tm1, 2));
        float mn0 = fmaxf(m0, tm0), mn1 = fmaxf(m1, tm1);
        float f0 = __expf(m0 - mn0), f1 = __expf(m1 - mn1);
        m0 = mn0; m1 = mn1;
        float rs0 = 0.f, rs1 = 0.f;
#pragma unroll
        for (int nf = 0; nf < 8; nf++) {
            S[nf][0] = __expf(S[nf][0] - mn0); rs0 += S[nf][0];
            S[nf][1] = __expf(S[nf][1] - mn0); rs0 += S[nf][1];
            S[nf][2] = __expf(S[nf][2] - mn1); rs1 += S[nf][2];
            S[nf][3] = __expf(S[nf][3] - mn1); rs1 += S[nf][3];
        }
        rs0 += __shfl_xor_sync(0xffffffffu, rs0, 1);
        rs0 += __shfl_xor_sync(0xffffffffu, rs0, 2);
        rs1 += __shfl_xor_sync(0xffffffffu, rs1, 1);
        rs1 += __shfl_xor_sync(0xffffffffu, rs1, 2);
        l0 = l0 * f0 + rs0;
        l1 = l1 * f1 + rs1;
#pragma unroll
        for (int nf = 0; nf < 8; nf++) {
            O[nf][0] *= f0; O[nf][1] *= f0;
            O[nf][2] *= f1; O[nf][3] *= f1;
        }

        // ---- O += P.V (3-product split) ----
#pragma unroll
        for (int kk = 0; kk < 4; kk++) {
            uint32_t ah[4], al[4];
            split2(S[2*kk][0],   S[2*kk][1],   ah[0], al[0]);
            split2(S[2*kk][2],   S[2*kk][3],   ah[1], al[1]);
            split2(S[2*kk+1][0], S[2*kk+1][1], ah[2], al[2]);
            split2(S[2*kk+1][2], S[2*kk+1][3], ah[3], al[3]);
            int bc16 = 2 * kk + bsel;
#pragma unroll
            for (int bp = 0; bp < 4; bp++) {
                int brow = bp * 16 + brow_b;
                uint32_t boff = (uint32_t)(brow * 128 + ((bc16 ^ (brow & 7)) << 4));
                uint32_t vh[4], vl[4];
                LDMX4(vh, kb + 16384u + boff);
                LDMX4(vl, kb + 24576u + boff);
                MMA16816(O[2*bp],   ah, vh[0], vh[1]);
                MMA16816(O[2*bp],   ah, vl[0], vl[1]);
                MMA16816(O[2*bp],   al, vh[0], vh[1]);
                MMA16816(O[2*bp+1], ah, vh[2], vh[3]);
                MMA16816(O[2*bp+1], ah, vl[2], vl[3]);
                MMA16816(O[2*bp+1], al, vh[2], vh[3]);
            }
        }
        __syncthreads();
    }

    // ---- epilogue: normalize + split-bf16 store to s_ahi/s_alo ----
    const int b = bh >> 4, h = bh & 15;
    const float inv0 = 1.0f / l0, inv1 = 1.0f / l1;
    const size_t mrow0 = (size_t)(b * SEQ + r0g) * DM;
    const size_t mrow1 = (size_t)(b * SEQ + r0g + 8) * DM;
    const int colb = h * HD + (lane & 3) * 2;
#pragma unroll
    for (int nf = 0; nf < 8; nf++) {
        int col = colb + nf * 8;
        uint32_t hi, lo;
        split2(O[nf][0] * inv0, O[nf][1] * inv0, hi, lo);
        *(uint32_t*)(s_ahi + mrow0 + col) = hi;
        *(uint32_t*)(s_alo + mrow0 + col) = lo;
        split2(O[nf][2] * inv1, O[nf][3] * inv1, hi, lo);
        *(uint32_t*)(s_ahi + mrow1 + col) = hi;
        *(uint32_t*)(s_alo + mrow1 + col) = lo;
    }
}

// ---------------------------------------------------------------------------
extern "C" void kernel_launch(void* const* d_in, const int* in_sizes, int n_in,
                              void* d_out, int out_size) {
    (void)out_size;
    const float* x = (const float*)d_in[0];
    const float* w_qkv = (const float*)d_in[1];
    const float* w_out = (const float*)d_in[2];
    for (int i = 0; i < n_in; i++) {
        if (in_sizes[i] == 8388608)      x     = (const float*)d_in[i];
        else if (in_sizes[i] == 3145728) w_qkv = (const float*)d_in[i];
        else if (in_sizes[i] == 1048576) w_out = (const float*)d_in[i];
    }
    float* out = (float*)d_out;

    void *p_xhi, *p_xlo, *p_whi, *p_wlo, *p_ohi, *p_olo, *p_ahi, *p_alo;
    cudaGetSymbolAddress(&p_xhi, s_xhi);
    cudaGetSymbolAddress(&p_xlo, s_xlo);
    cudaGetSymbolAddress(&p_whi, s_whi);
    cudaGetSymbolAddress(&p_wlo, s_wlo);
    cudaGetSymbolAddress(&p_ohi, s_ohi);
    cudaGetSymbolAddress(&p_olo, s_olo);
    cudaGetSymbolAddress(&p_ahi, s_ahi);
    cudaGetSymbolAddress(&p_alo, s_alo);

    cudaFuncSetAttribute(gemm_mma, cudaFuncAttributeMaxDynamicSharedMemorySize, GEMM_SMEM);
    cudaFuncSetAttribute(attn_mma, cudaFuncAttributeMaxDynamicSharedMemorySize, AT_SMEM);

    cvt_split<<<(MTOT*DM)/256, 256>>>(x, (__nv_bfloat16*)p_xhi, (__nv_bfloat16*)p_xlo, MTOT*DM);
    cvt_split<<<(3*DM*DM)/256, 256>>>(w_qkv, (__nv_bfloat16*)p_whi, (__nv_bfloat16*)p_wlo, 3*DM*DM);
    cvt_split<<<(DM*DM)/256, 256>>>(w_out, (__nv_bfloat16*)p_ohi, (__nv_bfloat16*)p_olo, DM*DM);

    gemm_mma<<<dim3(3*DM/128, MTOT/128), 256, GEMM_SMEM>>>(
        (const __nv_bfloat16*)p_xhi, (const __nv_bfloat16*)p_xlo,
        (const __nv_bfloat16*)p_whi, (const __nv_bfloat16*)p_wlo, nullptr, 1);

    rope_split<<<dim3((BATCH*NH*SEQ*32)/256, 2), 256>>>();
    transpose_v<<<dim3(BATCH*NH, SEQ/64), 256>>>();

    attn_mma<<<dim3(BATCH*NH, SEQ/128), 256, AT_SMEM>>>();

    gemm_mma<<<dim3(DM/128, MTOT/128), 256, GEMM_SMEM>>>(
        (const __nv_bfloat16*)p_ahi, (const __nv_bfloat16*)p_alo,
        (const __nv_bfloat16*)p_ohi, (const __nv_bfloat16*)p_olo, out, 0);
}

// round 10
// speedup vs baseline: 3.3606x; 1.1400x over previous
#include <cuda_runtime.h>
#include <cuda_bf16.h>
#include <math.h>
#include <stdint.h>

#define BATCH 4
#define SEQ   2048
#define DM    1024
#define NH    16
#define HD    64
#define MTOT  (BATCH*SEQ)   // 8192

// ---------------- scratch (__device__ statics; allocation-guard safe) -------
__device__ float g_q[(size_t)BATCH*NH*SEQ*HD];
__device__ float g_k[(size_t)BATCH*NH*SEQ*HD];
__device__ float g_v[(size_t)BATCH*NH*SEQ*HD];

__device__ __nv_bfloat16 s_xhi[(size_t)MTOT*DM];
__device__ __nv_bfloat16 s_xlo[(size_t)MTOT*DM];
__device__ __nv_bfloat16 s_whi[(size_t)3*DM*DM];
__device__ __nv_bfloat16 s_wlo[(size_t)3*DM*DM];
__device__ __nv_bfloat16 s_ohi[(size_t)DM*DM];
__device__ __nv_bfloat16 s_olo[(size_t)DM*DM];
__device__ __nv_bfloat16 s_ahi[(size_t)MTOT*DM];
__device__ __nv_bfloat16 s_alo[(size_t)MTOT*DM];

__device__ __nv_bfloat16 s_qhi[(size_t)BATCH*NH*SEQ*HD];
__device__ __nv_bfloat16 s_qlo[(size_t)BATCH*NH*SEQ*HD];
__device__ __nv_bfloat16 s_khi[(size_t)BATCH*NH*SEQ*HD];
__device__ __nv_bfloat16 s_klo[(size_t)BATCH*NH*SEQ*HD];
__device__ __nv_bfloat16 s_vthi[(size_t)BATCH*NH*HD*SEQ];  // [bh][d][s]
__device__ __nv_bfloat16 s_vtlo[(size_t)BATCH*NH*HD*SEQ];

// ---------------- helpers ----------------------------------------------------
__device__ __forceinline__ uint32_t smem_u32(const void* p) {
    uint32_t a;
    asm("{ .reg .u64 t; cvta.to.shared.u64 t, %1; cvt.u32.u64 %0, t; }"
        : "=r"(a) : "l"(p));
    return a;
}
#define LDMX4(d, a) \
    asm volatile("ldmatrix.sync.aligned.m8n8.x4.shared.b16 {%0,%1,%2,%3}, [%4];" \
                 : "=r"((d)[0]), "=r"((d)[1]), "=r"((d)[2]), "=r"((d)[3]) : "r"(a))
#define MMA16816(c, a, b0, b1) \
    asm volatile("mma.sync.aligned.m16n8k16.row.col.f32.bf16.bf16.f32 " \
                 "{%0,%1,%2,%3}, {%4,%5,%6,%7}, {%8,%9}, {%0,%1,%2,%3};" \
                 : "+f"((c)[0]), "+f"((c)[1]), "+f"((c)[2]), "+f"((c)[3]) \
                 : "r"((a)[0]), "r"((a)[1]), "r"((a)[2]), "r"((a)[3]), \
                   "r"(b0), "r"(b1))
#define CPASYNC16(sa, gp) \
    asm volatile("cp.async.cg.shared.global [%0], [%1], 16;" :: "r"(sa), "l"(gp))

__device__ __forceinline__ uint32_t pack_bf2(float a, float b) {
    __nv_bfloat162 t;
    t.x = __float2bfloat16(a);
    t.y = __float2bfloat16(b);
    return *reinterpret_cast<uint32_t*>(&t);
}
__device__ __forceinline__ void split2(float a, float b, uint32_t& hi, uint32_t& lo) {
    __nv_bfloat16 ah = __float2bfloat16(a), bh = __float2bfloat16(b);
    __nv_bfloat162 h; h.x = ah; h.y = bh;
    hi = *reinterpret_cast<uint32_t*>(&h);
    lo = pack_bf2(a - __bfloat162float(ah), b - __bfloat162float(bh));
}

// ---------------------------------------------------------------------------
// fp32 -> bf16 hi/lo split (inputs)
// ---------------------------------------------------------------------------
__global__ __launch_bounds__(256) void cvt_split(const float* __restrict__ src,
                                                 __nv_bfloat16* __restrict__ hi,
                                                 __nv_bfloat16* __restrict__ lo,
                                                 int n) {
    int i = blockIdx.x * 256 + threadIdx.x;
    if (i >= n) return;
    float x = src[i];
    __nv_bfloat16 h = __float2bfloat16(x);
    hi[i] = h;
    lo[i] = __float2bfloat16(x - __bfloat162float(h));
}

// ---------------------------------------------------------------------------
// Split-bf16 tensor-core GEMM. mode 0: OUT; mode 1: qkv scatter.
// 2 CTAs/SM (launch_bounds), A-fragments streamed to cut live registers.
// ---------------------------------------------------------------------------
#define GEMM_SMEM 65536

__device__ __forceinline__ void stage_chunk(
    uint32_t smbase, int p, int c,
    const __nv_bfloat16* s0, const __nv_bfloat16* s1,
    const __nv_bfloat16* s2, const __nv_bfloat16* s3, int tid)
{
    const __nv_bfloat16* srcs[4] = {s0, s1, s2, s3};
    const uint32_t bufb = smbase + (uint32_t)p * 32768u;
#pragma unroll
    for (int comp = 0; comp < 4; comp++) {
        const __nv_bfloat16* s = srcs[comp] + c * 32;
        const uint32_t db = bufb + (uint32_t)comp * 8192u;
#pragma unroll
        for (int t = 0; t < 2; t++) {
            int idx = tid + t * 256;
            int row = idx >> 2, c16 = idx & 3;
            const void* gp = s + (size_t)row * DM + c16 * 8;
            uint32_t sw = db + (uint32_t)(row * 64)
                        + ((uint32_t)(c16 ^ ((row >> 1) & 3)) << 4);
            CPASYNC16(sw, gp);
        }
    }
    asm volatile("cp.async.commit_group;" ::: "memory");
}

__device__ __forceinline__ float* qkv_ptr(int m, int col) {
    int which = col >> 10, h = (col & 1023) >> 6, dd = col & 63;
    float* dst = (which == 0) ? g_q : (which == 1) ? g_k : g_v;
    int b = m >> 11, s = m & 2047;
    return dst + (((size_t)(b * NH + h) * SEQ + s) * HD) + dd;
}

__global__ __launch_bounds__(256, 2) void gemm_mma(
    const __nv_bfloat16* __restrict__ Ahi, const __nv_bfloat16* __restrict__ Alo,
    const __nv_bfloat16* __restrict__ Bhi, const __nv_bfloat16* __restrict__ Blo,
    float* __restrict__ OUT, int mode)
{
    extern __shared__ __align__(128) char smraw[];
    const uint32_t smbase = smem_u32(smraw);
    const int tid  = threadIdx.x;
    const int wid  = tid >> 5;
    const int lane = tid & 31;
    const int wm   = wid >> 2;
    const int wn   = wid & 3;
    const int n0   = blockIdx.x * 128;
    const int m0   = blockIdx.y * 128;

    const __nv_bfloat16* gAhi = Ahi + (size_t)m0 * DM;
    const __nv_bfloat16* gAlo = Alo + (size_t)m0 * DM;
    const __nv_bfloat16* gBhi = Bhi + (size_t)n0 * DM;
    const __nv_bfloat16* gBlo = Blo + (size_t)n0 * DM;

    float C[4][4][4];
#pragma unroll
    for (int i = 0; i < 4; i++)
#pragma unroll
        for (int j = 0; j < 4; j++)
#pragma unroll
            for (int k = 0; k < 4; k++) C[i][j][k] = 0.f;

    const int g = lane >> 3, r = lane & 7;

    stage_chunk(smbase, 0, 0, gAhi, gAlo, gBhi, gBlo, tid);

    for (int c = 0; c < 32; c++) {
        const int p = c & 1;
        if (c < 31) {
            stage_chunk(smbase, p ^ 1, c + 1, gAhi, gAlo, gBhi, gBlo, tid);
            asm volatile("cp.async.wait_group 1;" ::: "memory");
        } else {
            asm volatile("cp.async.wait_group 0;" ::: "memory");
        }
        __syncthreads();

        const uint32_t ab = smbase + (uint32_t)p * 32768u;
#pragma unroll
        for (int kh = 0; kh < 2; kh++) {
            const int kkc = kh * 2;
            // B fragments first (16 live regs)
            uint32_t bhi[4][2], blo[4][2];
#pragma unroll
            for (int bp = 0; bp < 2; bp++) {
                int row = wn * 32 + bp * 16 + (g >> 1) * 8 + r;
                int c16 = kkc + (g & 1);
                uint32_t sw = (uint32_t)(row * 64)
                            + ((uint32_t)(c16 ^ ((row >> 1) & 3)) << 4);
                uint32_t t[4];
                LDMX4(t, ab + 16384u + sw);
                bhi[bp*2][0] = t[0]; bhi[bp*2][1] = t[1];
                bhi[bp*2+1][0] = t[2]; bhi[bp*2+1][1] = t[3];
                LDMX4(t, ab + 24576u + sw);
                blo[bp*2][0] = t[0]; blo[bp*2][1] = t[1];
                blo[bp*2+1][0] = t[2]; blo[bp*2+1][1] = t[3];
            }
            // Stream A fragments (8 live regs at a time)
#pragma unroll
            for (int mf = 0; mf < 4; mf++) {
                int row = wm * 64 + mf * 16 + (g & 1) * 8 + r;
                int c16 = kkc + (g >> 1);
                uint32_t sw = (uint32_t)(row * 64)
                            + ((uint32_t)(c16 ^ ((row >> 1) & 3)) << 4);
                uint32_t ah[4], al[4];
                LDMX4(ah, ab + sw);
                LDMX4(al, ab + 8192u + sw);
#pragma unroll
                for (int nf = 0; nf < 4; nf++) {
                    MMA16816(C[mf][nf], ah, bhi[nf][0], bhi[nf][1]);
                    MMA16816(C[mf][nf], ah, blo[nf][0], blo[nf][1]);
                    MMA16816(C[mf][nf], al, bhi[nf][0], bhi[nf][1]);
                }
            }
        }
        __syncthreads();
    }

#pragma unroll
    for (int mf = 0; mf < 4; mf++) {
#pragma unroll
        for (int nf = 0; nf < 4; nf++) {
            int row0 = m0 + wm * 64 + mf * 16 + (lane >> 2);
            int col  = n0 + wn * 32 + nf * 8 + (lane & 3) * 2;
            float2 v0 = make_float2(C[mf][nf][0], C[mf][nf][1]);
            float2 v1 = make_float2(C[mf][nf][2], C[mf][nf][3]);
            if (mode == 0) {
                *(float2*)(OUT + (size_t)row0 * DM + col) = v0;
                *(float2*)(OUT + (size_t)(row0 + 8) * DM + col) = v1;
            } else {
                *(float2*)qkv_ptr(row0, col) = v0;
                *(float2*)qkv_ptr(row0 + 8, col) = v1;
            }
        }
    }
}

// ---------------------------------------------------------------------------
// RoPE (neg-sin interleaved, validated) + split to bf16 hi/lo
// ---------------------------------------------------------------------------
__global__ __launch_bounds__(256) void rope_split() {
    const size_t idx = (size_t)blockIdx.x * 256 + threadIdx.x;
    const int p  = (int)(idx & 31);
    const int s  = (int)((idx >> 5) & 2047);
    const float* src = (blockIdx.y == 0) ? g_q : g_k;
    __nv_bfloat16* dhi = (blockIdx.y == 0) ? s_qhi : s_khi;
    __nv_bfloat16* dlo = (blockIdx.y == 0) ? s_qlo : s_klo;
    size_t base = (idx >> 5) * HD + 2 * p;
    float inv_f = expf((float)(2 * p) * -0.14391156831212787f);
    float ang = (float)s * inv_f;
    float cs, sn;
    sincosf(ang, &cs, &sn);
    float2 x = *(const float2*)(src + base);
    float y0 = x.x * cs + x.y * sn;
    float y1 = x.y * cs - x.x * sn;
    uint32_t hi, lo;
    split2(y0, y1, hi, lo);
    *(uint32_t*)(dhi + base) = hi;
    *(uint32_t*)(dlo + base) = lo;
}

// ---------------------------------------------------------------------------
// V transpose + split: g_v fp32 [bh][s][d] -> s_vthi/s_vtlo [bh][d][s]
// ---------------------------------------------------------------------------
__global__ __launch_bounds__(256) void transpose_v() {
    __shared__ float t[64][65];
    const int bh = blockIdx.x, s0 = blockIdx.y * 64;
    const int tid = threadIdx.x;
    const float* src = g_v + (size_t)bh * SEQ * HD + (size_t)s0 * HD;
#pragma unroll
    for (int i = 0; i < 4; i++) {
        int idx = tid + i * 256;
        int rr = idx >> 4, cc = (idx & 15) << 2;
        float4 v = *(const float4*)(src + rr * HD + cc);
        t[rr][cc] = v.x; t[rr][cc+1] = v.y; t[rr][cc+2] = v.z; t[rr][cc+3] = v.w;
    }
    __syncthreads();
    __nv_bfloat16* dhi = s_vthi + (size_t)bh * HD * SEQ + s0;
    __nv_bfloat16* dlo = s_vtlo + (size_t)bh * HD * SEQ + s0;
#pragma unroll
    for (int i = 0; i < 8; i++) {
        int idx = tid + i * 256;
        int d = idx >> 5, sp = (idx & 31) << 1;
        uint32_t hi, lo;
        split2(t[sp][d], t[sp+1][d], hi, lo);
        *(uint32_t*)(dhi + (size_t)d * SEQ + sp) = hi;
        *(uint32_t*)(dlo + (size_t)d * SEQ + sp) = lo;
    }
}

// ---------------------------------------------------------------------------
// Flash attention, split-bf16 mma.sync (verified r9), 2 CTAs/SM target.
// ---------------------------------------------------------------------------
#define AT_SMEM (32768 + 2*32768)

__device__ __forceinline__ void at_stage64(uint32_t dst, const __nv_bfloat16* src,
                                           int rowstride, int tid) {
#pragma unroll
    for (int t = 0; t < 2; t++) {
        int idx = tid + t * 256;
        int row = idx >> 3, c16 = idx & 7;
        const void* gp = src + (size_t)row * rowstride + c16 * 8;
        uint32_t sa = dst + (uint32_t)(row * 128 + ((c16 ^ (row & 7)) << 4));
        CPASYNC16(sa, gp);
    }
}

__global__ __launch_bounds__(256, 2) void attn_mma() {
    extern __shared__ __align__(128) char smraw[];
    const uint32_t sb = smem_u32(smraw);
    const int tid = threadIdx.x;
    const int wid = tid >> 5;
    const int lane = tid & 31;
    const int bh = blockIdx.x;
    const int qt = 15 - blockIdx.y;           // heavy tiles first
    const int q0 = qt * 128;
    const int nkt = 2 * qt + 2;

    const size_t qk_off = (size_t)bh * SEQ * HD;
    const size_t vt_off = (size_t)bh * HD * SEQ;

#pragma unroll
    for (int t = 0; t < 4; t++) {
        int idx = tid + t * 256;
        int row = idx >> 3, c16 = idx & 7;
        uint32_t sw = (uint32_t)(row * 128 + ((c16 ^ (row & 7)) << 4));
        CPASYNC16(sb + sw, s_qhi + qk_off + (size_t)(q0 + row) * HD + c16 * 8);
        CPASYNC16(sb + 16384u + sw, s_qlo + qk_off + (size_t)(q0 + row) * HD + c16 * 8);
    }
    {
        uint32_t d0 = sb + 32768u;
        at_stage64(d0,           s_khi + qk_off, HD, tid);
        at_stage64(d0 + 8192u,   s_klo + qk_off, HD, tid);
        at_stage64(d0 + 16384u,  s_vthi + vt_off, SEQ, tid);
        at_stage64(d0 + 24576u,  s_vtlo + vt_off, SEQ, tid);
    }
    asm volatile("cp.async.commit_group;" ::: "memory");

    float O[8][4];
#pragma unroll
    for (int nf = 0; nf < 8; nf++)
#pragma unroll
        for (int j = 0; j < 4; j++) O[nf][j] = 0.f;
    float m0 = -1e30f, m1 = -1e30f, l0 = 0.f, l1 = 0.f;

    const int r0g = q0 + wid * 16 + (lane >> 2);
    const int arow = wid * 16 + ((lane >> 3) & 1) * 8 + (lane & 7);
    const int brow_b = (lane & 7) + (lane >> 4) * 8;
    const int bsel = (lane >> 3) & 1;
    const int asel = lane >> 4;

    for (int kt = 0; kt < nkt; kt++) {
        const int p = kt & 1;
        const int k0 = kt * 64;
        asm volatile("cp.async.wait_group 0;" ::: "memory");
        __syncthreads();
        if (kt + 1 < nkt) {
            uint32_t dn = sb + 32768u + (uint32_t)(p ^ 1) * 32768u;
            int kn = (kt + 1) * 64;
            at_stage64(dn,          s_khi + qk_off + (size_t)kn * HD, HD, tid);
            at_stage64(dn + 8192u,  s_klo + qk_off + (size_t)kn * HD, HD, tid);
            at_stage64(dn + 16384u, s_vthi + vt_off + kn, SEQ, tid);
            at_stage64(dn + 24576u, s_vtlo + vt_off + kn, SEQ, tid);
            asm volatile("cp.async.commit_group;" ::: "memory");
        }
        const uint32_t kb = sb + 32768u + (uint32_t)p * 32768u;

        float S[8][4];
#pragma unroll
        for (int nf = 0; nf < 8; nf++)
#pragma unroll
            for (int j = 0; j < 4; j++) S[nf][j] = 0.f;
#pragma unroll
        for (int kh = 0; kh < 4; kh++) {
            int ac16 = 2 * kh + asel;
            uint32_t aoff = (uint32_t)(arow * 128 + ((ac16 ^ (arow & 7)) << 4));
            uint32_t qh[4], ql[4];
            LDMX4(qh, sb + aoff);
            LDMX4(ql, sb + 16384u + aoff);
            int bc16 = 2 * kh + bsel;
#pragma unroll
            for (int bp = 0; bp < 4; bp++) {
                int brow = bp * 16 + brow_b;
                uint32_t boff = (uint32_t)(brow * 128 + ((bc16 ^ (brow & 7)) << 4));
                uint32_t th[4], tl[4];
                LDMX4(th, kb + boff);
                LDMX4(tl, kb + 8192u + boff);
                MMA16816(S[2*bp],   qh, th[0], th[1]);
                MMA16816(S[2*bp],   qh, tl[0], tl[1]);
                MMA16816(S[2*bp],   ql, th[0], th[1]);
                MMA16816(S[2*bp+1], qh, th[2], th[3]);
                MMA16816(S[2*bp+1], qh, tl[2], tl[3]);
                MMA16816(S[2*bp+1], ql, th[2], th[3]);
            }
        }

        const bool msk = (k0 >= q0);
#pragma unroll
        for (int nf = 0; nf < 8; nf++)
#pragma unroll
            for (int j = 0; j < 4; j++) {
                float sv = S[nf][j] * 0.125f;
                if (msk) {
                    int col = k0 + nf * 8 + (lane & 3) * 2 + (j & 1);
                    int row = (j < 2) ? r0g : r0g + 8;
                    if (col > row) sv = -1e30f;
                }
                S[nf][j] = sv;
            }

        float tm0 = -1e30f, tm1 = -1e30f;
#pragma unroll
        for (int nf = 0; nf < 8; nf++) {
            tm0 = fmaxf(tm0, fmaxf(S[nf][0], S[nf][1]));
            tm1 = fmaxf(tm1, fmaxf(S[nf][2], S[nf][3]));
        }
        tm0 = fmaxf(tm0, __shfl_xor_sync(0xffffffffu, tm0, 1));
        tm0 = fmaxf(tm0, __shfl_xor_sync(0xffffffffu, tm0, 2));
        tm1 = fmaxf(tm1, __shfl_xor_sync(0xffffffffu, tm1, 1));
        tm1 = fmaxf(tm1, __shfl_xor_sync(0xffffffffu, tm1, 2));
        float mn0 = fmaxf(m0, tm0), mn1 = fmaxf(m1, tm1);
        float f0 = __expf(m0 - mn0), f1 = __expf(m1 - mn1);
        m0 = mn0; m1 = mn1;
        float rs0 = 0.f, rs1 = 0.f;
#pragma unroll
        for (int nf = 0; nf < 8; nf++) {
            S[nf][0] = __expf(S[nf][0] - mn0); rs0 += S[nf][0];
            S[nf][1] = __expf(S[nf][1] - mn0); rs0 += S[nf][1];
            S[nf][2] = __expf(S[nf][2] - mn1); rs1 += S[nf][2];
            S[nf][3] = __expf(S[nf][3] - mn1); rs1 += S[nf][3];
        }
        rs0 += __shfl_xor_sync(0xffffffffu, rs0, 1);
        rs0 += __shfl_xor_sync(0xffffffffu, rs0, 2);
        rs1 += __shfl_xor_sync(0xffffffffu, rs1, 1);
        rs1 += __shfl_xor_sync(0xffffffffu, rs1, 2);
        l0 = l0 * f0 + rs0;
        l1 = l1 * f1 + rs1;
#pragma unroll
        for (int nf = 0; nf < 8; nf++) {
            O[nf][0] *= f0; O[nf][1] *= f0;
            O[nf][2] *= f1; O[nf][3] *= f1;
        }

#pragma unroll
        for (int kk = 0; kk < 4; kk++) {
            uint32_t ah[4], al[4];
            split2(S[2*kk][0],   S[2*kk][1],   ah[0], al[0]);
            split2(S[2*kk][2],   S[2*kk][3],   ah[1], al[1]);
            split2(S[2*kk+1][0], S[2*kk+1][1], ah[2], al[2]);
            split2(S[2*kk+1][2], S[2*kk+1][3], ah[3], al[3]);
            int bc16 = 2 * kk + bsel;
#pragma unroll
            for (int bp = 0; bp < 4; bp++) {
                int brow = bp * 16 + brow_b;
                uint32_t boff = (uint32_t)(brow * 128 + ((bc16 ^ (brow & 7)) << 4));
                uint32_t vh[4], vl[4];
                LDMX4(vh, kb + 16384u + boff);
                LDMX4(vl, kb + 24576u + boff);
                MMA16816(O[2*bp],   ah, vh[0], vh[1]);
                MMA16816(O[2*bp],   ah, vl[0], vl[1]);
                MMA16816(O[2*bp],   al, vh[0], vh[1]);
                MMA16816(O[2*bp+1], ah, vh[2], vh[3]);
                MMA16816(O[2*bp+1], ah, vl[2], vl[3]);
                MMA16816(O[2*bp+1], al, vh[2], vh[3]);
            }
        }
        __syncthreads();
    }

    const int b = bh >> 4, h = bh & 15;
    const float inv0 = 1.0f / l0, inv1 = 1.0f / l1;
    const size_t mrow0 = (size_t)(b * SEQ + r0g) * DM;
    const size_t mrow1 = (size_t)(b * SEQ + r0g + 8) * DM;
    const int colb = h * HD + (lane & 3) * 2;
#pragma unroll
    for (int nf = 0; nf < 8; nf++) {
        int col = colb + nf * 8;
        uint32_t hi, lo;
        split2(O[nf][0] * inv0, O[nf][1] * inv0, hi, lo);
        *(uint32_t*)(s_ahi + mrow0 + col) = hi;
        *(uint32_t*)(s_alo + mrow0 + col) = lo;
        split2(O[nf][2] * inv1, O[nf][3] * inv1, hi, lo);
        *(uint32_t*)(s_ahi + mrow1 + col) = hi;
        *(uint32_t*)(s_alo + mrow1 + col) = lo;
    }
}

// ---------------------------------------------------------------------------
extern "C" void kernel_launch(void* const* d_in, const int* in_sizes, int n_in,
                              void* d_out, int out_size) {
    (void)out_size;
    const float* x = (const float*)d_in[0];
    const float* w_qkv = (const float*)d_in[1];
    const float* w_out = (const float*)d_in[2];
    for (int i = 0; i < n_in; i++) {
        if (in_sizes[i] == 8388608)      x     = (const float*)d_in[i];
        else if (in_sizes[i] == 3145728) w_qkv = (const float*)d_in[i];
        else if (in_sizes[i] == 1048576) w_out = (const float*)d_in[i];
    }
    float* out = (float*)d_out;

    void *p_xhi, *p_xlo, *p_whi, *p_wlo, *p_ohi, *p_olo, *p_ahi, *p_alo;
    cudaGetSymbolAddress(&p_xhi, s_xhi);
    cudaGetSymbolAddress(&p_xlo, s_xlo);
    cudaGetSymbolAddress(&p_whi, s_whi);
    cudaGetSymbolAddress(&p_wlo, s_wlo);
    cudaGetSymbolAddress(&p_ohi, s_ohi);
    cudaGetSymbolAddress(&p_olo, s_olo);
    cudaGetSymbolAddress(&p_ahi, s_ahi);
    cudaGetSymbolAddress(&p_alo, s_alo);

    cudaFuncSetAttribute(gemm_mma, cudaFuncAttributeMaxDynamicSharedMemorySize, GEMM_SMEM);
    cudaFuncSetAttribute(attn_mma, cudaFuncAttributeMaxDynamicSharedMemorySize, AT_SMEM);

    cvt_split<<<(MTOT*DM)/256, 256>>>(x, (__nv_bfloat16*)p_xhi, (__nv_bfloat16*)p_xlo, MTOT*DM);
    cvt_split<<<(3*DM*DM)/256, 256>>>(w_qkv, (__nv_bfloat16*)p_whi, (__nv_bfloat16*)p_wlo, 3*DM*DM);
    cvt_split<<<(DM*DM)/256, 256>>>(w_out, (__nv_bfloat16*)p_ohi, (__nv_bfloat16*)p_olo, DM*DM);

    gemm_mma<<<dim3(3*DM/128, MTOT/128), 256, GEMM_SMEM>>>(
        (const __nv_bfloat16*)p_xhi, (const __nv_bfloat16*)p_xlo,
        (const __nv_bfloat16*)p_whi, (const __nv_bfloat16*)p_wlo, nullptr, 1);

    rope_split<<<dim3((BATCH*NH*SEQ*32)/256, 2), 256>>>();
    transpose_v<<<dim3(BATCH*NH, SEQ/64), 256>>>();

    attn_mma<<<dim3(BATCH*NH, SEQ/128), 256, AT_SMEM>>>();

    gemm_mma<<<dim3(DM/128, MTOT/128), 256, GEMM_SMEM>>>(
        (const __nv_bfloat16*)p_ahi, (const __nv_bfloat16*)p_alo,
        (const __nv_bfloat16*)p_ohi, (const __nv_bfloat16*)p_olo, out, 0);
}

// round 11
// speedup vs baseline: 3.4448x; 1.0251x over previous
#include <cuda_runtime.h>
#include <cuda_bf16.h>
#include <math.h>
#include <stdint.h>

#define BATCH 4
#define SEQ   2048
#define DM    1024
#define NH    16
#define HD    64
#define MTOT  (BATCH*SEQ)   // 8192

// ---------------- scratch (__device__ statics; allocation-guard safe) -------
__device__ float g_v[(size_t)BATCH*NH*SEQ*HD];

__device__ __nv_bfloat16 s_xhi[(size_t)MTOT*DM];
__device__ __nv_bfloat16 s_xlo[(size_t)MTOT*DM];
__device__ __nv_bfloat16 s_whi[(size_t)3*DM*DM];
__device__ __nv_bfloat16 s_wlo[(size_t)3*DM*DM];
__device__ __nv_bfloat16 s_ohi[(size_t)DM*DM];
__device__ __nv_bfloat16 s_olo[(size_t)DM*DM];
__device__ __nv_bfloat16 s_ahi[(size_t)MTOT*DM];
__device__ __nv_bfloat16 s_alo[(size_t)MTOT*DM];

__device__ __nv_bfloat16 s_qhi[(size_t)BATCH*NH*SEQ*HD];
__device__ __nv_bfloat16 s_qlo[(size_t)BATCH*NH*SEQ*HD];
__device__ __nv_bfloat16 s_khi[(size_t)BATCH*NH*SEQ*HD];
__device__ __nv_bfloat16 s_klo[(size_t)BATCH*NH*SEQ*HD];
__device__ __nv_bfloat16 s_vthi[(size_t)BATCH*NH*HD*SEQ];  // [bh][d][s]
__device__ __nv_bfloat16 s_vtlo[(size_t)BATCH*NH*HD*SEQ];

// ---------------- helpers ----------------------------------------------------
__device__ __forceinline__ uint32_t smem_u32(const void* p) {
    uint32_t a;
    asm("{ .reg .u64 t; cvta.to.shared.u64 t, %1; cvt.u32.u64 %0, t; }"
        : "=r"(a) : "l"(p));
    return a;
}
#define LDMX4(d, a) \
    asm volatile("ldmatrix.sync.aligned.m8n8.x4.shared.b16 {%0,%1,%2,%3}, [%4];" \
                 : "=r"((d)[0]), "=r"((d)[1]), "=r"((d)[2]), "=r"((d)[3]) : "r"(a))
#define MMA16816(c, a, b0, b1) \
    asm volatile("mma.sync.aligned.m16n8k16.row.col.f32.bf16.bf16.f32 " \
                 "{%0,%1,%2,%3}, {%4,%5,%6,%7}, {%8,%9}, {%0,%1,%2,%3};" \
                 : "+f"((c)[0]), "+f"((c)[1]), "+f"((c)[2]), "+f"((c)[3]) \
                 : "r"((a)[0]), "r"((a)[1]), "r"((a)[2]), "r"((a)[3]), \
                   "r"(b0), "r"(b1))
#define CPASYNC16(sa, gp) \
    asm volatile("cp.async.cg.shared.global [%0], [%1], 16;" :: "r"(sa), "l"(gp))

__device__ __forceinline__ uint32_t pack_bf2(float a, float b) {
    __nv_bfloat162 t;
    t.x = __float2bfloat16(a);
    t.y = __float2bfloat16(b);
    return *reinterpret_cast<uint32_t*>(&t);
}
__device__ __forceinline__ void split2(float a, float b, uint32_t& hi, uint32_t& lo) {
    __nv_bfloat16 ah = __float2bfloat16(a), bh = __float2bfloat16(b);
    __nv_bfloat162 h; h.x = ah; h.y = bh;
    hi = *reinterpret_cast<uint32_t*>(&h);
    lo = pack_bf2(a - __bfloat162float(ah), b - __bfloat162float(bh));
}

// ---------------------------------------------------------------------------
// fp32 -> bf16 hi/lo split (inputs)
// ---------------------------------------------------------------------------
__global__ __launch_bounds__(256) void cvt_split(const float* __restrict__ src,
                                                 __nv_bfloat16* __restrict__ hi,
                                                 __nv_bfloat16* __restrict__ lo,
                                                 int n) {
    int i = blockIdx.x * 256 + threadIdx.x;
    if (i >= n) return;
    float x = src[i];
    __nv_bfloat16 h = __float2bfloat16(x);
    hi[i] = h;
    lo[i] = __float2bfloat16(x - __bfloat162float(h));
}

// ---------------------------------------------------------------------------
// Split-bf16 tensor-core GEMM. 3-stage cp.async ring, 1 barrier per K-chunk.
// mode 0: OUT store. mode 1: q/k -> RoPE+split to s_q*/s_k*; v -> g_v fp32.
// ---------------------------------------------------------------------------
#define GEMM_SMEM (3 * 32768)

__device__ __forceinline__ void stage_chunk(
    uint32_t smbase, int bufidx, int c,
    const __nv_bfloat16* s0, const __nv_bfloat16* s1,
    const __nv_bfloat16* s2, const __nv_bfloat16* s3, int tid)
{
    const __nv_bfloat16* srcs[4] = {s0, s1, s2, s3};
    const uint32_t bufb = smbase + (uint32_t)bufidx * 32768u;
#pragma unroll
    for (int comp = 0; comp < 4; comp++) {
        const __nv_bfloat16* s = srcs[comp] + c * 32;
        const uint32_t db = bufb + (uint32_t)comp * 8192u;
#pragma unroll
        for (int t = 0; t < 2; t++) {
            int idx = tid + t * 256;
            int row = idx >> 2, c16 = idx & 3;
            const void* gp = s + (size_t)row * DM + c16 * 8;
            uint32_t sw = db + (uint32_t)(row * 64)
                        + ((uint32_t)(c16 ^ ((row >> 1) & 3)) << 4);
            CPASYNC16(sw, gp);
        }
    }
    asm volatile("cp.async.commit_group;" ::: "memory");
}

__global__ __launch_bounds__(256, 2) void gemm_mma(
    const __nv_bfloat16* __restrict__ Ahi, const __nv_bfloat16* __restrict__ Alo,
    const __nv_bfloat16* __restrict__ Bhi, const __nv_bfloat16* __restrict__ Blo,
    float* __restrict__ OUT, int mode)
{
    extern __shared__ __align__(128) char smraw[];
    const uint32_t smbase = smem_u32(smraw);
    const int tid  = threadIdx.x;
    const int wid  = tid >> 5;
    const int lane = tid & 31;
    const int wm   = wid >> 2;
    const int wn   = wid & 3;
    const int n0   = blockIdx.x * 128;
    const int m0   = blockIdx.y * 128;

    const __nv_bfloat16* gAhi = Ahi + (size_t)m0 * DM;
    const __nv_bfloat16* gAlo = Alo + (size_t)m0 * DM;
    const __nv_bfloat16* gBhi = Bhi + (size_t)n0 * DM;
    const __nv_bfloat16* gBlo = Blo + (size_t)n0 * DM;

    float C[4][4][4];
#pragma unroll
    for (int i = 0; i < 4; i++)
#pragma unroll
        for (int j = 0; j < 4; j++)
#pragma unroll
            for (int k = 0; k < 4; k++) C[i][j][k] = 0.f;

    const int g = lane >> 3, r = lane & 7;

    stage_chunk(smbase, 0, 0, gAhi, gAlo, gBhi, gBlo, tid);
    stage_chunk(smbase, 1, 1, gAhi, gAlo, gBhi, gBlo, tid);

    for (int c = 0; c < 32; c++) {
        if (c < 31) {
            asm volatile("cp.async.wait_group 1;" ::: "memory");
        } else {
            asm volatile("cp.async.wait_group 0;" ::: "memory");
        }
        __syncthreads();                     // single barrier per chunk
        if (c + 2 < 32)
            stage_chunk(smbase, (c + 2) % 3, c + 2, gAhi, gAlo, gBhi, gBlo, tid);

        const uint32_t ab = smbase + (uint32_t)(c % 3) * 32768u;
#pragma unroll
        for (int kh = 0; kh < 2; kh++) {
            const int kkc = kh * 2;
            uint32_t bhi[4][2], blo[4][2];
#pragma unroll
            for (int bp = 0; bp < 2; bp++) {
                int row = wn * 32 + bp * 16 + (g >> 1) * 8 + r;
                int c16 = kkc + (g & 1);
                uint32_t sw = (uint32_t)(row * 64)
                            + ((uint32_t)(c16 ^ ((row >> 1) & 3)) << 4);
                uint32_t t[4];
                LDMX4(t, ab + 16384u + sw);
                bhi[bp*2][0] = t[0]; bhi[bp*2][1] = t[1];
                bhi[bp*2+1][0] = t[2]; bhi[bp*2+1][1] = t[3];
                LDMX4(t, ab + 24576u + sw);
                blo[bp*2][0] = t[0]; blo[bp*2][1] = t[1];
                blo[bp*2+1][0] = t[2]; blo[bp*2+1][1] = t[3];
            }
#pragma unroll
            for (int mf = 0; mf < 4; mf++) {
                int row = wm * 64 + mf * 16 + (g & 1) * 8 + r;
                int c16 = kkc + (g >> 1);
                uint32_t sw = (uint32_t)(row * 64)
                            + ((uint32_t)(c16 ^ ((row >> 1) & 3)) << 4);
                uint32_t ah[4], al[4];
                LDMX4(ah, ab + sw);
                LDMX4(al, ab + 8192u + sw);
#pragma unroll
                for (int nf = 0; nf < 4; nf++) {
                    MMA16816(C[mf][nf], ah, bhi[nf][0], bhi[nf][1]);
                    MMA16816(C[mf][nf], ah, blo[nf][0], blo[nf][1]);
                    MMA16816(C[mf][nf], al, bhi[nf][0], bhi[nf][1]);
                }
            }
        }
    }

    // ---------------- epilogue ----------------
#pragma unroll
    for (int mf = 0; mf < 4; mf++) {
#pragma unroll
        for (int nf = 0; nf < 4; nf++) {
            int row0 = m0 + wm * 64 + mf * 16 + (lane >> 2);
            int col  = n0 + wn * 32 + nf * 8 + (lane & 3) * 2;   // even
            if (mode == 0) {
                *(float2*)(OUT + (size_t)row0 * DM + col) =
                    make_float2(C[mf][nf][0], C[mf][nf][1]);
                *(float2*)(OUT + (size_t)(row0 + 8) * DM + col) =
                    make_float2(C[mf][nf][2], C[mf][nf][3]);
            } else {
                const int which = col >> 10;
                const int h  = (col & 1023) >> 6;
                const int dd = col & 63;
                if (which == 2) {
                    // V: fp32 store for transpose_v
#pragma unroll
                    for (int rr = 0; rr < 2; rr++) {
                        int row = row0 + rr * 8;
                        int b = row >> 11, s = row & 2047;
                        float* vp = g_v + (((size_t)(b * NH + h) * SEQ + s) * HD) + dd;
                        *(float2*)vp = make_float2(C[mf][nf][2*rr], C[mf][nf][2*rr+1]);
                    }
                } else {
                    // Q/K: RoPE (neg-sin interleaved, validated r6) + split
                    __nv_bfloat16* dhi = (which == 0) ? s_qhi : s_khi;
                    __nv_bfloat16* dlo = (which == 0) ? s_qlo : s_klo;
                    const float inv_f = expf((float)dd * -0.14391156831212787f);
#pragma unroll
                    for (int rr = 0; rr < 2; rr++) {
                        int row = row0 + rr * 8;
                        int b = row >> 11, s = row & 2047;
                        float cs, sn;
                        sincosf((float)s * inv_f, &cs, &sn);
                        float x0 = C[mf][nf][2*rr], x1 = C[mf][nf][2*rr+1];
                        float y0 = x0 * cs + x1 * sn;
                        float y1 = x1 * cs - x0 * sn;
                        uint32_t hi, lo;
                        split2(y0, y1, hi, lo);
                        size_t off = (((size_t)(b * NH + h) * SEQ + s) * HD) + dd;
                        *(uint32_t*)(dhi + off) = hi;
                        *(uint32_t*)(dlo + off) = lo;
                    }
                }
            }
        }
    }
}

// ---------------------------------------------------------------------------
// V transpose + split: g_v fp32 [bh][s][d] -> s_vthi/s_vtlo [bh][d][s]
// ---------------------------------------------------------------------------
__global__ __launch_bounds__(256) void transpose_v() {
    __shared__ float t[64][65];
    const int bh = blockIdx.x, s0 = blockIdx.y * 64;
    const int tid = threadIdx.x;
    const float* src = g_v + (size_t)bh * SEQ * HD + (size_t)s0 * HD;
#pragma unroll
    for (int i = 0; i < 4; i++) {
        int idx = tid + i * 256;
        int rr = idx >> 4, cc = (idx & 15) << 2;
        float4 v = *(const float4*)(src + rr * HD + cc);
        t[rr][cc] = v.x; t[rr][cc+1] = v.y; t[rr][cc+2] = v.z; t[rr][cc+3] = v.w;
    }
    __syncthreads();
    __nv_bfloat16* dhi = s_vthi + (size_t)bh * HD * SEQ + s0;
    __nv_bfloat16* dlo = s_vtlo + (size_t)bh * HD * SEQ + s0;
#pragma unroll
    for (int i = 0; i < 8; i++) {
        int idx = tid + i * 256;
        int d = idx >> 5, sp = (idx & 31) << 1;
        uint32_t hi, lo;
        split2(t[sp][d], t[sp+1][d], hi, lo);
        *(uint32_t*)(dhi + (size_t)d * SEQ + sp) = hi;
        *(uint32_t*)(dlo + (size_t)d * SEQ + sp) = lo;
    }
}

// ---------------------------------------------------------------------------
// Flash attention, split-bf16 mma.sync (verified r9/r10).
// ---------------------------------------------------------------------------
#define AT_SMEM (32768 + 2*32768)

__device__ __forceinline__ void at_stage64(uint32_t dst, const __nv_bfloat16* src,
                                           int rowstride, int tid) {
#pragma unroll
    for (int t = 0; t < 2; t++) {
        int idx = tid + t * 256;
        int row = idx >> 3, c16 = idx & 7;
        const void* gp = src + (size_t)row * rowstride + c16 * 8;
        uint32_t sa = dst + (uint32_t)(row * 128 + ((c16 ^ (row & 7)) << 4));
        CPASYNC16(sa, gp);
    }
}

__global__ __launch_bounds__(256, 2) void attn_mma() {
    extern __shared__ __align__(128) char smraw[];
    const uint32_t sb = smem_u32(smraw);
    const int tid = threadIdx.x;
    const int wid = tid >> 5;
    const int lane = tid & 31;
    const int bh = blockIdx.x;
    const int qt = 15 - blockIdx.y;           // heavy tiles first
    const int q0 = qt * 128;
    const int nkt = 2 * qt + 2;

    const size_t qk_off = (size_t)bh * SEQ * HD;
    const size_t vt_off = (size_t)bh * HD * SEQ;

#pragma unroll
    for (int t = 0; t < 4; t++) {
        int idx = tid + t * 256;
        int row = idx >> 3, c16 = idx & 7;
        uint32_t sw = (uint32_t)(row * 128 + ((c16 ^ (row & 7)) << 4));
        CPASYNC16(sb + sw, s_qhi + qk_off + (size_t)(q0 + row) * HD + c16 * 8);
        CPASYNC16(sb + 16384u + sw, s_qlo + qk_off + (size_t)(q0 + row) * HD + c16 * 8);
    }
    {
        uint32_t d0 = sb + 32768u;
        at_stage64(d0,           s_khi + qk_off, HD, tid);
        at_stage64(d0 + 8192u,   s_klo + qk_off, HD, tid);
        at_stage64(d0 + 16384u,  s_vthi + vt_off, SEQ, tid);
        at_stage64(d0 + 24576u,  s_vtlo + vt_off, SEQ, tid);
    }
    asm volatile("cp.async.commit_group;" ::: "memory");

    float O[8][4];
#pragma unroll
    for (int nf = 0; nf < 8; nf++)
#pragma unroll
        for (int j = 0; j < 4; j++) O[nf][j] = 0.f;
    float m0 = -1e30f, m1 = -1e30f, l0 = 0.f, l1 = 0.f;

    const int r0g = q0 + wid * 16 + (lane >> 2);
    const int arow = wid * 16 + ((lane >> 3) & 1) * 8 + (lane & 7);
    const int brow_b = (lane & 7) + (lane >> 4) * 8;
    const int bsel = (lane >> 3) & 1;
    const int asel = lane >> 4;

    for (int kt = 0; kt < nkt; kt++) {
        const int p = kt & 1;
        const int k0 = kt * 64;
        asm volatile("cp.async.wait_group 0;" ::: "memory");
        __syncthreads();
        if (kt + 1 < nkt) {
            uint32_t dn = sb + 32768u + (uint32_t)(p ^ 1) * 32768u;
            int kn = (kt + 1) * 64;
            at_stage64(dn,          s_khi + qk_off + (size_t)kn * HD, HD, tid);
            at_stage64(dn + 8192u,  s_klo + qk_off + (size_t)kn * HD, HD, tid);
            at_stage64(dn + 16384u, s_vthi + vt_off + kn, SEQ, tid);
            at_stage64(dn + 24576u, s_vtlo + vt_off + kn, SEQ, tid);
            asm volatile("cp.async.commit_group;" ::: "memory");
        }
        const uint32_t kb = sb + 32768u + (uint32_t)p * 32768u;

        float S[8][4];
#pragma unroll
        for (int nf = 0; nf < 8; nf++)
#pragma unroll
            for (int j = 0; j < 4; j++) S[nf][j] = 0.f;
#pragma unroll
        for (int kh = 0; kh < 4; kh++) {
            int ac16 = 2 * kh + asel;
            uint32_t aoff = (uint32_t)(arow * 128 + ((ac16 ^ (arow & 7)) << 4));
            uint32_t qh[4], ql[4];
            LDMX4(qh, sb + aoff);
            LDMX4(ql, sb + 16384u + aoff);
            int bc16 = 2 * kh + bsel;
#pragma unroll
            for (int bp = 0; bp < 4; bp++) {
                int brow = bp * 16 + brow_b;
                uint32_t boff = (uint32_t)(brow * 128 + ((bc16 ^ (brow & 7)) << 4));
                uint32_t th[4], tl[4];
                LDMX4(th, kb + boff);
                LDMX4(tl, kb + 8192u + boff);
                MMA16816(S[2*bp],   qh, th[0], th[1]);
                MMA16816(S[2*bp],   qh, tl[0], tl[1]);
                MMA16816(S[2*bp],   ql, th[0], th[1]);
                MMA16816(S[2*bp+1], qh, th[2], th[3]);
                MMA16816(S[2*bp+1], qh, tl[2], tl[3]);
                MMA16816(S[2*bp+1], ql, th[2], th[3]);
            }
        }

        const bool msk = (k0 >= q0);
#pragma unroll
        for (int nf = 0; nf < 8; nf++)
#pragma unroll
            for (int j = 0; j < 4; j++) {
                float sv = S[nf][j] * 0.125f;
                if (msk) {
                    int col = k0 + nf * 8 + (lane & 3) * 2 + (j & 1);
                    int row = (j < 2) ? r0g : r0g + 8;
                    if (col > row) sv = -1e30f;
                }
                S[nf][j] = sv;
            }

        float tm0 = -1e30f, tm1 = -1e30f;
#pragma unroll
        for (int nf = 0; nf < 8; nf++) {
            tm0 = fmaxf(tm0, fmaxf(S[nf][0], S[nf][1]));
            tm1 = fmaxf(tm1, fmaxf(S[nf][2], S[nf][3]));
        }
        tm0 = fmaxf(tm0, __shfl_xor_sync(0xffffffffu, tm0, 1));
        tm0 = fmaxf(tm0, __shfl_xor_sync(0xffffffffu, tm0, 2));
        tm1 = fmaxf(tm1, __shfl_xor_sync(0xffffffffu, tm1, 1));
        tm1 = fmaxf(tm1, __shfl_xor_sync(0xffffffffu, tm1, 2));
        float mn0 = fmaxf(m0, tm0), mn1 = fmaxf(m1, tm1);
        float f0 = __expf(m0 - mn0), f1 = __expf(m1 - mn1);
        m0 = mn0; m1 = mn1;
        float rs0 = 0.f, rs1 = 0.f;
#pragma unroll
        for (int nf = 0; nf < 8; nf++) {
            S[nf][0] = __expf(S[nf][0] - mn0); rs0 += S[nf][0];
            S[nf][1] = __expf(S[nf][1] - mn0); rs0 += S[nf][1];
            S[nf][2] = __expf(S[nf][2] - mn1); rs1 += S[nf][2];
            S[nf][3] = __expf(S[nf][3] - mn1); rs1 += S[nf][3];
        }
        rs0 += __shfl_xor_sync(0xffffffffu, rs0, 1);
        rs0 += __shfl_xor_sync(0xffffffffu, rs0, 2);
        rs1 += __shfl_xor_sync(0xffffffffu, rs1, 1);
        rs1 += __shfl_xor_sync(0xffffffffu, rs1, 2);
        l0 = l0 * f0 + rs0;
        l1 = l1 * f1 + rs1;
#pragma unroll
        for (int nf = 0; nf < 8; nf++) {
            O[nf][0] *= f0; O[nf][1] *= f0;
            O[nf][2] *= f1; O[nf][3] *= f1;
        }

#pragma unroll
        for (int kk = 0; kk < 4; kk++) {
            uint32_t ah[4], al[4];
            split2(S[2*kk][0],   S[2*kk][1],   ah[0], al[0]);
            split2(S[2*kk][2],   S[2*kk][3],   ah[1], al[1]);
            split2(S[2*kk+1][0], S[2*kk+1][1], ah[2], al[2]);
            split2(S[2*kk+1][2], S[2*kk+1][3], ah[3], al[3]);
            int bc16 = 2 * kk + bsel;
#pragma unroll
            for (int bp = 0; bp < 4; bp++) {
                int brow = bp * 16 + brow_b;
                uint32_t boff = (uint32_t)(brow * 128 + ((bc16 ^ (brow & 7)) << 4));
                uint32_t vh[4], vl[4];
                LDMX4(vh, kb + 16384u + boff);
                LDMX4(vl, kb + 24576u + boff);
                MMA16816(O[2*bp],   ah, vh[0], vh[1]);
                MMA16816(O[2*bp],   ah, vl[0], vl[1]);
                MMA16816(O[2*bp],   al, vh[0], vh[1]);
                MMA16816(O[2*bp+1], ah, vh[2], vh[3]);
                MMA16816(O[2*bp+1], ah, vl[2], vl[3]);
                MMA16816(O[2*bp+1], al, vh[2], vh[3]);
            }
        }
        __syncthreads();
    }

    const int b = bh >> 4, h = bh & 15;
    const float inv0 = 1.0f / l0, inv1 = 1.0f / l1;
    const size_t mrow0 = (size_t)(b * SEQ + r0g) * DM;
    const size_t mrow1 = (size_t)(b * SEQ + r0g + 8) * DM;
    const int colb = h * HD + (lane & 3) * 2;
#pragma unroll
    for (int nf = 0; nf < 8; nf++) {
        int col = colb + nf * 8;
        uint32_t hi, lo;
        split2(O[nf][0] * inv0, O[nf][1] * inv0, hi, lo);
        *(uint32_t*)(s_ahi + mrow0 + col) = hi;
        *(uint32_t*)(s_alo + mrow0 + col) = lo;
        split2(O[nf][2] * inv1, O[nf][3] * inv1, hi, lo);
        *(uint32_t*)(s_ahi + mrow1 + col) = hi;
        *(uint32_t*)(s_alo + mrow1 + col) = lo;
    }
}

// ---------------------------------------------------------------------------
extern "C" void kernel_launch(void* const* d_in, const int* in_sizes, int n_in,
                              void* d_out, int out_size) {
    (void)out_size;
    const float* x = (const float*)d_in[0];
    const float* w_qkv = (const float*)d_in[1];
    const float* w_out = (const float*)d_in[2];
    for (int i = 0; i < n_in; i++) {
        if (in_sizes[i] == 8388608)      x     = (const float*)d_in[i];
        else if (in_sizes[i] == 3145728) w_qkv = (const float*)d_in[i];
        else if (in_sizes[i] == 1048576) w_out = (const float*)d_in[i];
    }
    float* out = (float*)d_out;

    void *p_xhi, *p_xlo, *p_whi, *p_wlo, *p_ohi, *p_olo, *p_ahi, *p_alo;
    cudaGetSymbolAddress(&p_xhi, s_xhi);
    cudaGetSymbolAddress(&p_xlo, s_xlo);
    cudaGetSymbolAddress(&p_whi, s_whi);
    cudaGetSymbolAddress(&p_wlo, s_wlo);
    cudaGetSymbolAddress(&p_ohi, s_ohi);
    cudaGetSymbolAddress(&p_olo, s_olo);
    cudaGetSymbolAddress(&p_ahi, s_ahi);
    cudaGetSymbolAddress(&p_alo, s_alo);

    cudaFuncSetAttribute(gemm_mma, cudaFuncAttributeMaxDynamicSharedMemorySize, GEMM_SMEM);
    cudaFuncSetAttribute(attn_mma, cudaFuncAttributeMaxDynamicSharedMemorySize, AT_SMEM);

    cvt_split<<<(MTOT*DM)/256, 256>>>(x, (__nv_bfloat16*)p_xhi, (__nv_bfloat16*)p_xlo, MTOT*DM);
    cvt_split<<<(3*DM*DM)/256, 256>>>(w_qkv, (__nv_bfloat16*)p_whi, (__nv_bfloat16*)p_wlo, 3*DM*DM);
    cvt_split<<<(DM*DM)/256, 256>>>(w_out, (__nv_bfloat16*)p_ohi, (__nv_bfloat16*)p_olo, DM*DM);

    gemm_mma<<<dim3(3*DM/128, MTOT/128), 256, GEMM_SMEM>>>(
        (const __nv_bfloat16*)p_xhi, (const __nv_bfloat16*)p_xlo,
        (const __nv_bfloat16*)p_whi, (const __nv_bfloat16*)p_wlo, nullptr, 1);

    transpose_v<<<dim3(BATCH*NH, SEQ/64), 256>>>();

    attn_mma<<<dim3(BATCH*NH, SEQ/128), 256, AT_SMEM>>>();

    gemm_mma<<<dim3(DM/128, MTOT/128), 256, GEMM_SMEM>>>(
        (const __nv_bfloat16*)p_ahi, (const __nv_bfloat16*)p_alo,
        (const __nv_bfloat16*)p_ohi, (const __nv_bfloat16*)p_olo, out, 0);
}

// round 12
// speedup vs baseline: 3.4786x; 1.0098x over previous
#include <cuda_runtime.h>
#include <cuda_bf16.h>
#include <math.h>
#include <stdint.h>

#define BATCH 4
#define SEQ   2048
#define DM    1024
#define NH    16
#define HD    64
#define MTOT  (BATCH*SEQ)   // 8192

// ---------------- scratch (__device__ statics; allocation-guard safe) -------
__device__ float g_v[(size_t)BATCH*NH*SEQ*HD];

__device__ __nv_bfloat16 s_xhi[(size_t)MTOT*DM];
__device__ __nv_bfloat16 s_xlo[(size_t)MTOT*DM];
__device__ __nv_bfloat16 s_whi[(size_t)3*DM*DM];
__device__ __nv_bfloat16 s_wlo[(size_t)3*DM*DM];
__device__ __nv_bfloat16 s_ohi[(size_t)DM*DM];
__device__ __nv_bfloat16 s_olo[(size_t)DM*DM];
__device__ __nv_bfloat16 s_ahi[(size_t)MTOT*DM];
__device__ __nv_bfloat16 s_alo[(size_t)MTOT*DM];

__device__ __nv_bfloat16 s_qhi[(size_t)BATCH*NH*SEQ*HD];
__device__ __nv_bfloat16 s_qlo[(size_t)BATCH*NH*SEQ*HD];
__device__ __nv_bfloat16 s_khi[(size_t)BATCH*NH*SEQ*HD];
__device__ __nv_bfloat16 s_klo[(size_t)BATCH*NH*SEQ*HD];
__device__ __nv_bfloat16 s_vthi[(size_t)BATCH*NH*HD*SEQ];  // [bh][d][s]
__device__ __nv_bfloat16 s_vtlo[(size_t)BATCH*NH*HD*SEQ];

// ---------------- helpers ----------------------------------------------------
__device__ __forceinline__ uint32_t smem_u32(const void* p) {
    uint32_t a;
    asm("{ .reg .u64 t; cvta.to.shared.u64 t, %1; cvt.u32.u64 %0, t; }"
        : "=r"(a) : "l"(p));
    return a;
}
#define LDMX4(d, a) \
    asm volatile("ldmatrix.sync.aligned.m8n8.x4.shared.b16 {%0,%1,%2,%3}, [%4];" \
                 : "=r"((d)[0]), "=r"((d)[1]), "=r"((d)[2]), "=r"((d)[3]) : "r"(a))
#define MMA16816(c, a, b0, b1) \
    asm volatile("mma.sync.aligned.m16n8k16.row.col.f32.bf16.bf16.f32 " \
                 "{%0,%1,%2,%3}, {%4,%5,%6,%7}, {%8,%9}, {%0,%1,%2,%3};" \
                 : "+f"((c)[0]), "+f"((c)[1]), "+f"((c)[2]), "+f"((c)[3]) \
                 : "r"((a)[0]), "r"((a)[1]), "r"((a)[2]), "r"((a)[3]), \
                   "r"(b0), "r"(b1))
#define CPASYNC16(sa, gp) \
    asm volatile("cp.async.cg.shared.global [%0], [%1], 16;" :: "r"(sa), "l"(gp))

__device__ __forceinline__ uint32_t pack_bf2(float a, float b) {
    __nv_bfloat162 t;
    t.x = __float2bfloat16(a);
    t.y = __float2bfloat16(b);
    return *reinterpret_cast<uint32_t*>(&t);
}
__device__ __forceinline__ void split2(float a, float b, uint32_t& hi, uint32_t& lo) {
    __nv_bfloat16 ah = __float2bfloat16(a), bh = __float2bfloat16(b);
    __nv_bfloat162 h; h.x = ah; h.y = bh;
    hi = *reinterpret_cast<uint32_t*>(&h);
    lo = pack_bf2(a - __bfloat162float(ah), b - __bfloat162float(bh));
}

// ---------------------------------------------------------------------------
// fp32 -> bf16 hi/lo split (inputs)
// ---------------------------------------------------------------------------
__global__ __launch_bounds__(256) void cvt_split(const float* __restrict__ src,
                                                 __nv_bfloat16* __restrict__ hi,
                                                 __nv_bfloat16* __restrict__ lo,
                                                 int n) {
    int i = blockIdx.x * 256 + threadIdx.x;
    if (i >= n) return;
    float x = src[i];
    __nv_bfloat16 h = __float2bfloat16(x);
    hi[i] = h;
    lo[i] = __float2bfloat16(x - __bfloat162float(h));
}

// ---------------------------------------------------------------------------
// Split-bf16 tensor-core GEMM. r10 2-stage double-buffer loop (proven),
// product-major MMA order (acc reuse distance 4).
// mode 0: OUT store. mode 1: q/k -> RoPE+split; v -> g_v fp32.
// ---------------------------------------------------------------------------
#define GEMM_SMEM 65536

__device__ __forceinline__ void stage_chunk(
    uint32_t smbase, int p, int c,
    const __nv_bfloat16* s0, const __nv_bfloat16* s1,
    const __nv_bfloat16* s2, const __nv_bfloat16* s3, int tid)
{
    const __nv_bfloat16* srcs[4] = {s0, s1, s2, s3};
    const uint32_t bufb = smbase + (uint32_t)p * 32768u;
#pragma unroll
    for (int comp = 0; comp < 4; comp++) {
        const __nv_bfloat16* s = srcs[comp] + c * 32;
        const uint32_t db = bufb + (uint32_t)comp * 8192u;
#pragma unroll
        for (int t = 0; t < 2; t++) {
            int idx = tid + t * 256;
            int row = idx >> 2, c16 = idx & 3;
            const void* gp = s + (size_t)row * DM + c16 * 8;
            uint32_t sw = db + (uint32_t)(row * 64)
                        + ((uint32_t)(c16 ^ ((row >> 1) & 3)) << 4);
            CPASYNC16(sw, gp);
        }
    }
    asm volatile("cp.async.commit_group;" ::: "memory");
}

__global__ __launch_bounds__(256, 2) void gemm_mma(
    const __nv_bfloat16* __restrict__ Ahi, const __nv_bfloat16* __restrict__ Alo,
    const __nv_bfloat16* __restrict__ Bhi, const __nv_bfloat16* __restrict__ Blo,
    float* __restrict__ OUT, int mode)
{
    extern __shared__ __align__(128) char smraw[];
    const uint32_t smbase = smem_u32(smraw);
    const int tid  = threadIdx.x;
    const int wid  = tid >> 5;
    const int lane = tid & 31;
    const int wm   = wid >> 2;
    const int wn   = wid & 3;
    const int n0   = blockIdx.x * 128;
    const int m0   = blockIdx.y * 128;

    const __nv_bfloat16* gAhi = Ahi + (size_t)m0 * DM;
    const __nv_bfloat16* gAlo = Alo + (size_t)m0 * DM;
    const __nv_bfloat16* gBhi = Bhi + (size_t)n0 * DM;
    const __nv_bfloat16* gBlo = Blo + (size_t)n0 * DM;

    float C[4][4][4];
#pragma unroll
    for (int i = 0; i < 4; i++)
#pragma unroll
        for (int j = 0; j < 4; j++)
#pragma unroll
            for (int k = 0; k < 4; k++) C[i][j][k] = 0.f;

    const int g = lane >> 3, r = lane & 7;

    stage_chunk(smbase, 0, 0, gAhi, gAlo, gBhi, gBlo, tid);

    for (int c = 0; c < 32; c++) {
        const int p = c & 1;
        if (c < 31) {
            stage_chunk(smbase, p ^ 1, c + 1, gAhi, gAlo, gBhi, gBlo, tid);
            asm volatile("cp.async.wait_group 1;" ::: "memory");
        } else {
            asm volatile("cp.async.wait_group 0;" ::: "memory");
        }
        __syncthreads();

        const uint32_t ab = smbase + (uint32_t)p * 32768u;
#pragma unroll
        for (int kh = 0; kh < 2; kh++) {
            const int kkc = kh * 2;
            uint32_t bhi[4][2], blo[4][2];
#pragma unroll
            for (int bp = 0; bp < 2; bp++) {
                int row = wn * 32 + bp * 16 + (g >> 1) * 8 + r;
                int c16 = kkc + (g & 1);
                uint32_t sw = (uint32_t)(row * 64)
                            + ((uint32_t)(c16 ^ ((row >> 1) & 3)) << 4);
                uint32_t t[4];
                LDMX4(t, ab + 16384u + sw);
                bhi[bp*2][0] = t[0]; bhi[bp*2][1] = t[1];
                bhi[bp*2+1][0] = t[2]; bhi[bp*2+1][1] = t[3];
                LDMX4(t, ab + 24576u + sw);
                blo[bp*2][0] = t[0]; blo[bp*2][1] = t[1];
                blo[bp*2+1][0] = t[2]; blo[bp*2+1][1] = t[3];
            }
#pragma unroll
            for (int mf = 0; mf < 4; mf++) {
                int row = wm * 64 + mf * 16 + (g & 1) * 8 + r;
                int c16 = kkc + (g >> 1);
                uint32_t sw = (uint32_t)(row * 64)
                            + ((uint32_t)(c16 ^ ((row >> 1) & 3)) << 4);
                uint32_t ah[4], al[4];
                LDMX4(ah, ab + sw);
                LDMX4(al, ab + 8192u + sw);
                // product-major: same-acc reuse distance = 4
#pragma unroll
                for (int nf = 0; nf < 4; nf++)
                    MMA16816(C[mf][nf], ah, bhi[nf][0], bhi[nf][1]);
#pragma unroll
                for (int nf = 0; nf < 4; nf++)
                    MMA16816(C[mf][nf], ah, blo[nf][0], blo[nf][1]);
#pragma unroll
                for (int nf = 0; nf < 4; nf++)
                    MMA16816(C[mf][nf], al, bhi[nf][0], bhi[nf][1]);
            }
        }
        __syncthreads();
    }

    // ---------------- epilogue ----------------
#pragma unroll
    for (int mf = 0; mf < 4; mf++) {
#pragma unroll
        for (int nf = 0; nf < 4; nf++) {
            int row0 = m0 + wm * 64 + mf * 16 + (lane >> 2);
            int col  = n0 + wn * 32 + nf * 8 + (lane & 3) * 2;   // even
            if (mode == 0) {
                *(float2*)(OUT + (size_t)row0 * DM + col) =
                    make_float2(C[mf][nf][0], C[mf][nf][1]);
                *(float2*)(OUT + (size_t)(row0 + 8) * DM + col) =
                    make_float2(C[mf][nf][2], C[mf][nf][3]);
            } else {
                const int which = col >> 10;
                const int h  = (col & 1023) >> 6;
                const int dd = col & 63;
                if (which == 2) {
#pragma unroll
                    for (int rr = 0; rr < 2; rr++) {
                        int row = row0 + rr * 8;
                        int b = row >> 11, s = row & 2047;
                        float* vp = g_v + (((size_t)(b * NH + h) * SEQ + s) * HD) + dd;
                        *(float2*)vp = make_float2(C[mf][nf][2*rr], C[mf][nf][2*rr+1]);
                    }
                } else {
                    // Q/K: RoPE (neg-sin interleaved, validated r6) + split
                    __nv_bfloat16* dhi = (which == 0) ? s_qhi : s_khi;
                    __nv_bfloat16* dlo = (which == 0) ? s_qlo : s_klo;
                    const float inv_f = expf((float)dd * -0.14391156831212787f);
#pragma unroll
                    for (int rr = 0; rr < 2; rr++) {
                        int row = row0 + rr * 8;
                        int b = row >> 11, s = row & 2047;
                        float cs, sn;
                        sincosf((float)s * inv_f, &cs, &sn);
                        float x0 = C[mf][nf][2*rr], x1 = C[mf][nf][2*rr+1];
                        float y0 = x0 * cs + x1 * sn;
                        float y1 = x1 * cs - x0 * sn;
                        uint32_t hi, lo;
                        split2(y0, y1, hi, lo);
                        size_t off = (((size_t)(b * NH + h) * SEQ + s) * HD) + dd;
                        *(uint32_t*)(dhi + off) = hi;
                        *(uint32_t*)(dlo + off) = lo;
                    }
                }
            }
        }
    }
}

// ---------------------------------------------------------------------------
// V transpose + split: g_v fp32 [bh][s][d] -> s_vthi/s_vtlo [bh][d][s]
// ---------------------------------------------------------------------------
__global__ __launch_bounds__(256) void transpose_v() {
    __shared__ float t[64][65];
    const int bh = blockIdx.x, s0 = blockIdx.y * 64;
    const int tid = threadIdx.x;
    const float* src = g_v + (size_t)bh * SEQ * HD + (size_t)s0 * HD;
#pragma unroll
    for (int i = 0; i < 4; i++) {
        int idx = tid + i * 256;
        int rr = idx >> 4, cc = (idx & 15) << 2;
        float4 v = *(const float4*)(src + rr * HD + cc);
        t[rr][cc] = v.x; t[rr][cc+1] = v.y; t[rr][cc+2] = v.z; t[rr][cc+3] = v.w;
    }
    __syncthreads();
    __nv_bfloat16* dhi = s_vthi + (size_t)bh * HD * SEQ + s0;
    __nv_bfloat16* dlo = s_vtlo + (size_t)bh * HD * SEQ + s0;
#pragma unroll
    for (int i = 0; i < 8; i++) {
        int idx = tid + i * 256;
        int d = idx >> 5, sp = (idx & 31) << 1;
        uint32_t hi, lo;
        split2(t[sp][d], t[sp+1][d], hi, lo);
        *(uint32_t*)(dhi + (size_t)d * SEQ + sp) = hi;
        *(uint32_t*)(dlo + (size_t)d * SEQ + sp) = lo;
    }
}

// ---------------------------------------------------------------------------
// Flash attention, split-bf16 mma.sync. Single barrier per K-tile,
// interleaved acc chains, warp-level skip of fully-masked diagonal warps.
// ---------------------------------------------------------------------------
#define AT_SMEM (32768 + 2*32768)

__device__ __forceinline__ void at_stage64(uint32_t dst, const __nv_bfloat16* src,
                                           int rowstride, int tid) {
#pragma unroll
    for (int t = 0; t < 2; t++) {
        int idx = tid + t * 256;
        int row = idx >> 3, c16 = idx & 7;
        const void* gp = src + (size_t)row * rowstride + c16 * 8;
        uint32_t sa = dst + (uint32_t)(row * 128 + ((c16 ^ (row & 7)) << 4));
        CPASYNC16(sa, gp);
    }
}

__global__ __launch_bounds__(256, 2) void attn_mma() {
    extern __shared__ __align__(128) char smraw[];
    const uint32_t sb = smem_u32(smraw);
    const int tid = threadIdx.x;
    const int wid = tid >> 5;
    const int lane = tid & 31;
    const int bh = blockIdx.x;
    const int qt = 15 - blockIdx.y;           // heavy tiles first
    const int q0 = qt * 128;
    const int nkt = 2 * qt + 2;

    const size_t qk_off = (size_t)bh * SEQ * HD;
    const size_t vt_off = (size_t)bh * HD * SEQ;

#pragma unroll
    for (int t = 0; t < 4; t++) {
        int idx = tid + t * 256;
        int row = idx >> 3, c16 = idx & 7;
        uint32_t sw = (uint32_t)(row * 128 + ((c16 ^ (row & 7)) << 4));
        CPASYNC16(sb + sw, s_qhi + qk_off + (size_t)(q0 + row) * HD + c16 * 8);
        CPASYNC16(sb + 16384u + sw, s_qlo + qk_off + (size_t)(q0 + row) * HD + c16 * 8);
    }
    {
        uint32_t d0 = sb + 32768u;
        at_stage64(d0,           s_khi + qk_off, HD, tid);
        at_stage64(d0 + 8192u,   s_klo + qk_off, HD, tid);
        at_stage64(d0 + 16384u,  s_vthi + vt_off, SEQ, tid);
        at_stage64(d0 + 24576u,  s_vtlo + vt_off, SEQ, tid);
    }
    asm volatile("cp.async.commit_group;" ::: "memory");

    float O[8][4];
#pragma unroll
    for (int nf = 0; nf < 8; nf++)
#pragma unroll
        for (int j = 0; j < 4; j++) O[nf][j] = 0.f;
    float m0 = -1e30f, m1 = -1e30f, l0 = 0.f, l1 = 0.f;

    const int r0g = q0 + wid * 16 + (lane >> 2);
    const int arow = wid * 16 + ((lane >> 3) & 1) * 8 + (lane & 7);
    const int brow_b = (lane & 7) + (lane >> 4) * 8;
    const int bsel = (lane >> 3) & 1;
    const int asel = lane >> 4;

    for (int kt = 0; kt < nkt; kt++) {
        const int p = kt & 1;
        const int k0 = kt * 64;
        asm volatile("cp.async.wait_group 0;" ::: "memory");
        __syncthreads();   // single barrier: all warps done with kt-1, tile kt ready
        if (kt + 1 < nkt) {
            uint32_t dn = sb + 32768u + (uint32_t)(p ^ 1) * 32768u;
            int kn = (kt + 1) * 64;
            at_stage64(dn,          s_khi + qk_off + (size_t)kn * HD, HD, tid);
            at_stage64(dn + 8192u,  s_klo + qk_off + (size_t)kn * HD, HD, tid);
            at_stage64(dn + 16384u, s_vthi + vt_off + kn, SEQ, tid);
            at_stage64(dn + 24576u, s_vtlo + vt_off + kn, SEQ, tid);
            asm volatile("cp.async.commit_group;" ::: "memory");
        }

        // warp-level skip: this warp's 16 q-rows all < k0 -> tile fully masked
        if (q0 + wid * 16 + 15 < k0) continue;

        const uint32_t kb = sb + 32768u + (uint32_t)p * 32768u;

        float S[8][4];
#pragma unroll
        for (int nf = 0; nf < 8; nf++)
#pragma unroll
            for (int j = 0; j < 4; j++) S[nf][j] = 0.f;
#pragma unroll
        for (int kh = 0; kh < 4; kh++) {
            int ac16 = 2 * kh + asel;
            uint32_t aoff = (uint32_t)(arow * 128 + ((ac16 ^ (arow & 7)) << 4));
            uint32_t qh[4], ql[4];
            LDMX4(qh, sb + aoff);
            LDMX4(ql, sb + 16384u + aoff);
            int bc16 = 2 * kh + bsel;
#pragma unroll
            for (int bp = 0; bp < 4; bp++) {
                int brow = bp * 16 + brow_b;
                uint32_t boff = (uint32_t)(brow * 128 + ((bc16 ^ (brow & 7)) << 4));
                uint32_t th[4], tl[4];
                LDMX4(th, kb + boff);
                LDMX4(tl, kb + 8192u + boff);
                // interleaved acc chains (distance 2)
                MMA16816(S[2*bp],   qh, th[0], th[1]);
                MMA16816(S[2*bp+1], qh, th[2], th[3]);
                MMA16816(S[2*bp],   qh, tl[0], tl[1]);
                MMA16816(S[2*bp+1], qh, tl[2], tl[3]);
                MMA16816(S[2*bp],   ql, th[0], th[1]);
                MMA16816(S[2*bp+1], ql, th[2], th[3]);
            }
        }

        const bool msk = (k0 >= q0);
#pragma unroll
        for (int nf = 0; nf < 8; nf++)
#pragma unroll
            for (int j = 0; j < 4; j++) {
                float sv = S[nf][j] * 0.125f;
                if (msk) {
                    int col = k0 + nf * 8 + (lane & 3) * 2 + (j & 1);
                    int row = (j < 2) ? r0g : r0g + 8;
                    if (col > row) sv = -1e30f;
                }
                S[nf][j] = sv;
            }

        float tm0 = -1e30f, tm1 = -1e30f;
#pragma unroll
        for (int nf = 0; nf < 8; nf++) {
            tm0 = fmaxf(tm0, fmaxf(S[nf][0], S[nf][1]));
            tm1 = fmaxf(tm1, fmaxf(S[nf][2], S[nf][3]));
        }
        tm0 = fmaxf(tm0, __shfl_xor_sync(0xffffffffu, tm0, 1));
        tm0 = fmaxf(tm0, __shfl_xor_sync(0xffffffffu, tm0, 2));
        tm1 = fmaxf(tm1, __shfl_xor_sync(0xffffffffu, tm1, 1));
        tm1 = fmaxf(tm1, __shfl_xor_sync(0xffffffffu, tm1, 2));
        float mn0 = fmaxf(m0, tm0), mn1 = fmaxf(m1, tm1);
        float f0 = __expf(m0 - mn0), f1 = __expf(m1 - mn1);
        m0 = mn0; m1 = mn1;
        float rs0 = 0.f, rs1 = 0.f;
#pragma unroll
        for (int nf = 0; nf < 8; nf++) {
            S[nf][0] = __expf(S[nf][0] - mn0); rs0 += S[nf][0];
            S[nf][1] = __expf(S[nf][1] - mn0); rs0 += S[nf][1];
            S[nf][2] = __expf(S[nf][2] - mn1); rs1 += S[nf][2];
            S[nf][3] = __expf(S[nf][3] - mn1); rs1 += S[nf][3];
        }
        rs0 += __shfl_xor_sync(0xffffffffu, rs0, 1);
        rs0 += __shfl_xor_sync(0xffffffffu, rs0, 2);
        rs1 += __shfl_xor_sync(0xffffffffu, rs1, 1);
        rs1 += __shfl_xor_sync(0xffffffffu, rs1, 2);
        l0 = l0 * f0 + rs0;
        l1 = l1 * f1 + rs1;
#pragma unroll
        for (int nf = 0; nf < 8; nf++) {
            O[nf][0] *= f0; O[nf][1] *= f0;
            O[nf][2] *= f1; O[nf][3] *= f1;
        }

#pragma unroll
        for (int kk = 0; kk < 4; kk++) {
            uint32_t ah[4], al[4];
            split2(S[2*kk][0],   S[2*kk][1],   ah[0], al[0]);
            split2(S[2*kk][2],   S[2*kk][3],   ah[1], al[1]);
            split2(S[2*kk+1][0], S[2*kk+1][1], ah[2], al[2]);
            split2(S[2*kk+1][2], S[2*kk+1][3], ah[3], al[3]);
            int bc16 = 2 * kk + bsel;
#pragma unroll
            for (int bp = 0; bp < 4; bp++) {
                int brow = bp * 16 + brow_b;
                uint32_t boff = (uint32_t)(brow * 128 + ((bc16 ^ (brow & 7)) << 4));
                uint32_t vh[4], vl[4];
                LDMX4(vh, kb + 16384u + boff);
                LDMX4(vl, kb + 24576u + boff);
                // interleaved acc chains (distance 2)
                MMA16816(O[2*bp],   ah, vh[0], vh[1]);
                MMA16816(O[2*bp+1], ah, vh[2], vh[3]);
                MMA16816(O[2*bp],   ah, vl[0], vl[1]);
                MMA16816(O[2*bp+1], ah, vl[2], vl[3]);
                MMA16816(O[2*bp],   al, vh[0], vh[1]);
                MMA16816(O[2*bp+1], al, vh[2], vh[3]);
            }
        }
    }

    const int b = bh >> 4, h = bh & 15;
    const float inv0 = 1.0f / l0, inv1 = 1.0f / l1;
    const size_t mrow0 = (size_t)(b * SEQ + r0g) * DM;
    const size_t mrow1 = (size_t)(b * SEQ + r0g + 8) * DM;
    const int colb = h * HD + (lane & 3) * 2;
#pragma unroll
    for (int nf = 0; nf < 8; nf++) {
        int col = colb + nf * 8;
        uint32_t hi, lo;
        split2(O[nf][0] * inv0, O[nf][1] * inv0, hi, lo);
        *(uint32_t*)(s_ahi + mrow0 + col) = hi;
        *(uint32_t*)(s_alo + mrow0 + col) = lo;
        split2(O[nf][2] * inv1, O[nf][3] * inv1, hi, lo);
        *(uint32_t*)(s_ahi + mrow1 + col) = hi;
        *(uint32_t*)(s_alo + mrow1 + col) = lo;
    }
}

// ---------------------------------------------------------------------------
extern "C" void kernel_launch(void* const* d_in, const int* in_sizes, int n_in,
                              void* d_out, int out_size) {
    (void)out_size;
    const float* x = (const float*)d_in[0];
    const float* w_qkv = (const float*)d_in[1];
    const float* w_out = (const float*)d_in[2];
    for (int i = 0; i < n_in; i++) {
        if (in_sizes[i] == 8388608)      x     = (const float*)d_in[i];
        else if (in_sizes[i] == 3145728) w_qkv = (const float*)d_in[i];
        else if (in_sizes[i] == 1048576) w_out = (const float*)d_in[i];
    }
    float* out = (float*)d_out;

    void *p_xhi, *p_xlo, *p_whi, *p_wlo, *p_ohi, *p_olo, *p_ahi, *p_alo;
    cudaGetSymbolAddress(&p_xhi, s_xhi);
    cudaGetSymbolAddress(&p_xlo, s_xlo);
    cudaGetSymbolAddress(&p_whi, s_whi);
    cudaGetSymbolAddress(&p_wlo, s_wlo);
    cudaGetSymbolAddress(&p_ohi, s_ohi);
    cudaGetSymbolAddress(&p_olo, s_olo);
    cudaGetSymbolAddress(&p_ahi, s_ahi);
    cudaGetSymbolAddress(&p_alo, s_alo);

    cudaFuncSetAttribute(gemm_mma, cudaFuncAttributeMaxDynamicSharedMemorySize, GEMM_SMEM);
    cudaFuncSetAttribute(attn_mma, cudaFuncAttributeMaxDynamicSharedMemorySize, AT_SMEM);

    cvt_split<<<(MTOT*DM)/256, 256>>>(x, (__nv_bfloat16*)p_xhi, (__nv_bfloat16*)p_xlo, MTOT*DM);
    cvt_split<<<(3*DM*DM)/256, 256>>>(w_qkv, (__nv_bfloat16*)p_whi, (__nv_bfloat16*)p_wlo, 3*DM*DM);
    cvt_split<<<(DM*DM)/256, 256>>>(w_out, (__nv_bfloat16*)p_ohi, (__nv_bfloat16*)p_olo, DM*DM);

    gemm_mma<<<dim3(3*DM/128, MTOT/128), 256, GEMM_SMEM>>>(
        (const __nv_bfloat16*)p_xhi, (const __nv_bfloat16*)p_xlo,
        (const __nv_bfloat16*)p_whi, (const __nv_bfloat16*)p_wlo, nullptr, 1);

    transpose_v<<<dim3(BATCH*NH, SEQ/64), 256>>>();

    attn_mma<<<dim3(BATCH*NH, SEQ/128), 256, AT_SMEM>>>();

    gemm_mma<<<dim3(DM/128, MTOT/128), 256, GEMM_SMEM>>>(
        (const __nv_bfloat16*)p_ahi, (const __nv_bfloat16*)p_alo,
        (const __nv_bfloat16*)p_ohi, (const __nv_bfloat16*)p_olo, out, 0);
}

// round 13
// speedup vs baseline: 3.5140x; 1.0102x over previous
#include <cuda_runtime.h>
#include <cuda_bf16.h>
#include <math.h>
#include <stdint.h>

#define BATCH 4
#define SEQ   2048
#define DM    1024
#define NH    16
#define HD    64
#define MTOT  (BATCH*SEQ)   // 8192

// ---------------- scratch (__device__ statics; allocation-guard safe) -------
__device__ float g_v[(size_t)BATCH*NH*SEQ*HD];

__device__ __nv_bfloat16 s_xhi[(size_t)MTOT*DM];
__device__ __nv_bfloat16 s_xlo[(size_t)MTOT*DM];
__device__ __nv_bfloat16 s_whi[(size_t)3*DM*DM];
__device__ __nv_bfloat16 s_wlo[(size_t)3*DM*DM];
__device__ __nv_bfloat16 s_ohi[(size_t)DM*DM];
__device__ __nv_bfloat16 s_olo[(size_t)DM*DM];
__device__ __nv_bfloat16 s_ahi[(size_t)MTOT*DM];
__device__ __nv_bfloat16 s_alo[(size_t)MTOT*DM];

__device__ __nv_bfloat16 s_qhi[(size_t)BATCH*NH*SEQ*HD];
__device__ __nv_bfloat16 s_qlo[(size_t)BATCH*NH*SEQ*HD];
__device__ __nv_bfloat16 s_khi[(size_t)BATCH*NH*SEQ*HD];
__device__ __nv_bfloat16 s_klo[(size_t)BATCH*NH*SEQ*HD];
__device__ __nv_bfloat16 s_vthi[(size_t)BATCH*NH*HD*SEQ];  // [bh][d][s]
__device__ __nv_bfloat16 s_vtlo[(size_t)BATCH*NH*HD*SEQ];

// ---------------- helpers ----------------------------------------------------
__device__ __forceinline__ uint32_t smem_u32(const void* p) {
    uint32_t a;
    asm("{ .reg .u64 t; cvta.to.shared.u64 t, %1; cvt.u32.u64 %0, t; }"
        : "=r"(a) : "l"(p));
    return a;
}
#define LDMX4(d, a) \
    asm volatile("ldmatrix.sync.aligned.m8n8.x4.shared.b16 {%0,%1,%2,%3}, [%4];" \
                 : "=r"((d)[0]), "=r"((d)[1]), "=r"((d)[2]), "=r"((d)[3]) : "r"(a))
#define MMA16816(c, a, b0, b1) \
    asm volatile("mma.sync.aligned.m16n8k16.row.col.f32.bf16.bf16.f32 " \
                 "{%0,%1,%2,%3}, {%4,%5,%6,%7}, {%8,%9}, {%0,%1,%2,%3};" \
                 : "+f"((c)[0]), "+f"((c)[1]), "+f"((c)[2]), "+f"((c)[3]) \
                 : "r"((a)[0]), "r"((a)[1]), "r"((a)[2]), "r"((a)[3]), \
                   "r"(b0), "r"(b1))
#define CPASYNC16(sa, gp) \
    asm volatile("cp.async.cg.shared.global [%0], [%1], 16;" :: "r"(sa), "l"(gp))

__device__ __forceinline__ uint32_t pack_bf2(float a, float b) {
    __nv_bfloat162 t;
    t.x = __float2bfloat16(a);
    t.y = __float2bfloat16(b);
    return *reinterpret_cast<uint32_t*>(&t);
}
__device__ __forceinline__ void split2(float a, float b, uint32_t& hi, uint32_t& lo) {
    __nv_bfloat16 ah = __float2bfloat16(a), bh = __float2bfloat16(b);
    __nv_bfloat162 h; h.x = ah; h.y = bh;
    hi = *reinterpret_cast<uint32_t*>(&h);
    lo = pack_bf2(a - __bfloat162float(ah), b - __bfloat162float(bh));
}

// ---------------------------------------------------------------------------
// fp32 -> bf16 hi/lo split of all three inputs in ONE launch
// ---------------------------------------------------------------------------
#define N_X (MTOT*DM)        // 8388608
#define N_W (3*DM*DM)        // 3145728
#define N_O (DM*DM)          // 1048576

__global__ __launch_bounds__(256) void cvt_split3(
    const float* __restrict__ x, const float* __restrict__ wq,
    const float* __restrict__ wo)
{
    int i = blockIdx.x * 256 + threadIdx.x;
    const float* src;
    __nv_bfloat16 *hi, *lo;
    int j;
    if (i < N_X)              { src = x;  hi = s_xhi; lo = s_xlo; j = i; }
    else if (i < N_X + N_W)   { src = wq; hi = s_whi; lo = s_wlo; j = i - N_X; }
    else                      { src = wo; hi = s_ohi; lo = s_olo; j = i - N_X - N_W; }
    float v = src[j];
    __nv_bfloat16 h = __float2bfloat16(v);
    hi[j] = h;
    lo[j] = __float2bfloat16(v - __bfloat162float(h));
}

// ---------------------------------------------------------------------------
// Split-bf16 tensor-core GEMM. 2-stage double buffer, ONE barrier per chunk
// (attention-proven ordering: stage AFTER wait+barrier).
// mode 0: OUT store. mode 1: q/k -> RoPE+split; v -> g_v fp32.
// ---------------------------------------------------------------------------
#define GEMM_SMEM 65536

__device__ __forceinline__ void stage_chunk(
    uint32_t smbase, int p, int c,
    const __nv_bfloat16* s0, const __nv_bfloat16* s1,
    const __nv_bfloat16* s2, const __nv_bfloat16* s3, int tid)
{
    const __nv_bfloat16* srcs[4] = {s0, s1, s2, s3};
    const uint32_t bufb = smbase + (uint32_t)p * 32768u;
#pragma unroll
    for (int comp = 0; comp < 4; comp++) {
        const __nv_bfloat16* s = srcs[comp] + c * 32;
        const uint32_t db = bufb + (uint32_t)comp * 8192u;
#pragma unroll
        for (int t = 0; t < 2; t++) {
            int idx = tid + t * 256;
            int row = idx >> 2, c16 = idx & 3;
            const void* gp = s + (size_t)row * DM + c16 * 8;
            uint32_t sw = db + (uint32_t)(row * 64)
                        + ((uint32_t)(c16 ^ ((row >> 1) & 3)) << 4);
            CPASYNC16(sw, gp);
        }
    }
    asm volatile("cp.async.commit_group;" ::: "memory");
}

__global__ __launch_bounds__(256, 2) void gemm_mma(
    const __nv_bfloat16* __restrict__ Ahi, const __nv_bfloat16* __restrict__ Alo,
    const __nv_bfloat16* __restrict__ Bhi, const __nv_bfloat16* __restrict__ Blo,
    float* __restrict__ OUT, int mode)
{
    extern __shared__ __align__(128) char smraw[];
    const uint32_t smbase = smem_u32(smraw);
    const int tid  = threadIdx.x;
    const int wid  = tid >> 5;
    const int lane = tid & 31;
    const int wm   = wid >> 2;
    const int wn   = wid & 3;
    const int n0   = blockIdx.x * 128;
    const int m0   = blockIdx.y * 128;

    const __nv_bfloat16* gAhi = Ahi + (size_t)m0 * DM;
    const __nv_bfloat16* gAlo = Alo + (size_t)m0 * DM;
    const __nv_bfloat16* gBhi = Bhi + (size_t)n0 * DM;
    const __nv_bfloat16* gBlo = Blo + (size_t)n0 * DM;

    float C[4][4][4];
#pragma unroll
    for (int i = 0; i < 4; i++)
#pragma unroll
        for (int j = 0; j < 4; j++)
#pragma unroll
            for (int k = 0; k < 4; k++) C[i][j][k] = 0.f;

    const int g = lane >> 3, r = lane & 7;

    stage_chunk(smbase, 0, 0, gAhi, gAlo, gBhi, gBlo, tid);

    for (int c = 0; c < 32; c++) {
        const int p = c & 1;
        asm volatile("cp.async.wait_group 0;" ::: "memory");
        __syncthreads();   // all warps done with chunk c-1; chunk c resident
        if (c + 1 < 32)
            stage_chunk(smbase, p ^ 1, c + 1, gAhi, gAlo, gBhi, gBlo, tid);

        const uint32_t ab = smbase + (uint32_t)p * 32768u;
#pragma unroll
        for (int kh = 0; kh < 2; kh++) {
            const int kkc = kh * 2;
            uint32_t bhi[4][2], blo[4][2];
#pragma unroll
            for (int bp = 0; bp < 2; bp++) {
                int row = wn * 32 + bp * 16 + (g >> 1) * 8 + r;
                int c16 = kkc + (g & 1);
                uint32_t sw = (uint32_t)(row * 64)
                            + ((uint32_t)(c16 ^ ((row >> 1) & 3)) << 4);
                uint32_t t[4];
                LDMX4(t, ab + 16384u + sw);
                bhi[bp*2][0] = t[0]; bhi[bp*2][1] = t[1];
                bhi[bp*2+1][0] = t[2]; bhi[bp*2+1][1] = t[3];
                LDMX4(t, ab + 24576u + sw);
                blo[bp*2][0] = t[0]; blo[bp*2][1] = t[1];
                blo[bp*2+1][0] = t[2]; blo[bp*2+1][1] = t[3];
            }
#pragma unroll
            for (int mf = 0; mf < 4; mf++) {
                int row = wm * 64 + mf * 16 + (g & 1) * 8 + r;
                int c16 = kkc + (g >> 1);
                uint32_t sw = (uint32_t)(row * 64)
                            + ((uint32_t)(c16 ^ ((row >> 1) & 3)) << 4);
                uint32_t ah[4], al[4];
                LDMX4(ah, ab + sw);
                LDMX4(al, ab + 8192u + sw);
#pragma unroll
                for (int nf = 0; nf < 4; nf++) {
                    MMA16816(C[mf][nf], ah, bhi[nf][0], bhi[nf][1]);
                    MMA16816(C[mf][nf], ah, blo[nf][0], blo[nf][1]);
                    MMA16816(C[mf][nf], al, bhi[nf][0], bhi[nf][1]);
                }
            }
        }
    }

    // ---------------- epilogue ----------------
#pragma unroll
    for (int mf = 0; mf < 4; mf++) {
#pragma unroll
        for (int nf = 0; nf < 4; nf++) {
            int row0 = m0 + wm * 64 + mf * 16 + (lane >> 2);
            int col  = n0 + wn * 32 + nf * 8 + (lane & 3) * 2;   // even
            if (mode == 0) {
                *(float2*)(OUT + (size_t)row0 * DM + col) =
                    make_float2(C[mf][nf][0], C[mf][nf][1]);
                *(float2*)(OUT + (size_t)(row0 + 8) * DM + col) =
                    make_float2(C[mf][nf][2], C[mf][nf][3]);
            } else {
                const int which = col >> 10;
                const int h  = (col & 1023) >> 6;
                const int dd = col & 63;
                if (which == 2) {
#pragma unroll
                    for (int rr = 0; rr < 2; rr++) {
                        int row = row0 + rr * 8;
                        int b = row >> 11, s = row & 2047;
                        float* vp = g_v + (((size_t)(b * NH + h) * SEQ + s) * HD) + dd;
                        *(float2*)vp = make_float2(C[mf][nf][2*rr], C[mf][nf][2*rr+1]);
                    }
                } else {
                    // Q/K: RoPE (neg-sin interleaved, validated r6) + split
                    __nv_bfloat16* dhi = (which == 0) ? s_qhi : s_khi;
                    __nv_bfloat16* dlo = (which == 0) ? s_qlo : s_klo;
                    const float inv_f = expf((float)dd * -0.14391156831212787f);
#pragma unroll
                    for (int rr = 0; rr < 2; rr++) {
                        int row = row0 + rr * 8;
                        int b = row >> 11, s = row & 2047;
                        float cs, sn;
                        sincosf((float)s * inv_f, &cs, &sn);
                        float x0 = C[mf][nf][2*rr], x1 = C[mf][nf][2*rr+1];
                        float y0 = x0 * cs + x1 * sn;
                        float y1 = x1 * cs - x0 * sn;
                        uint32_t hi, lo;
                        split2(y0, y1, hi, lo);
                        size_t off = (((size_t)(b * NH + h) * SEQ + s) * HD) + dd;
                        *(uint32_t*)(dhi + off) = hi;
                        *(uint32_t*)(dlo + off) = lo;
                    }
                }
            }
        }
    }
}

// ---------------------------------------------------------------------------
// V transpose + split: g_v fp32 [bh][s][d] -> s_vthi/s_vtlo [bh][d][s]
// ---------------------------------------------------------------------------
__global__ __launch_bounds__(256) void transpose_v() {
    __shared__ float t[64][65];
    const int bh = blockIdx.x, s0 = blockIdx.y * 64;
    const int tid = threadIdx.x;
    const float* src = g_v + (size_t)bh * SEQ * HD + (size_t)s0 * HD;
#pragma unroll
    for (int i = 0; i < 4; i++) {
        int idx = tid + i * 256;
        int rr = idx >> 4, cc = (idx & 15) << 2;
        float4 v = *(const float4*)(src + rr * HD + cc);
        t[rr][cc] = v.x; t[rr][cc+1] = v.y; t[rr][cc+2] = v.z; t[rr][cc+3] = v.w;
    }
    __syncthreads();
    __nv_bfloat16* dhi = s_vthi + (size_t)bh * HD * SEQ + s0;
    __nv_bfloat16* dlo = s_vtlo + (size_t)bh * HD * SEQ + s0;
#pragma unroll
    for (int i = 0; i < 8; i++) {
        int idx = tid + i * 256;
        int d = idx >> 5, sp = (idx & 31) << 1;
        uint32_t hi, lo;
        split2(t[sp][d], t[sp+1][d], hi, lo);
        *(uint32_t*)(dhi + (size_t)d * SEQ + sp) = hi;
        *(uint32_t*)(dlo + (size_t)d * SEQ + sp) = lo;
    }
}

// ---------------------------------------------------------------------------
// Flash attention, split-bf16 mma.sync. Base-2 softmax, single barrier/tile,
// warp-level diagonal skip.
// ---------------------------------------------------------------------------
#define AT_SMEM (32768 + 2*32768)
#define SCL2 0.18033688011112042f   /* 0.125 * log2(e) */

__device__ __forceinline__ void at_stage64(uint32_t dst, const __nv_bfloat16* src,
                                           int rowstride, int tid) {
#pragma unroll
    for (int t = 0; t < 2; t++) {
        int idx = tid + t * 256;
        int row = idx >> 3, c16 = idx & 7;
        const void* gp = src + (size_t)row * rowstride + c16 * 8;
        uint32_t sa = dst + (uint32_t)(row * 128 + ((c16 ^ (row & 7)) << 4));
        CPASYNC16(sa, gp);
    }
}

__global__ __launch_bounds__(256, 2) void attn_mma() {
    extern __shared__ __align__(128) char smraw[];
    const uint32_t sb = smem_u32(smraw);
    const int tid = threadIdx.x;
    const int wid = tid >> 5;
    const int lane = tid & 31;
    const int bh = blockIdx.x;
    const int qt = 15 - blockIdx.y;           // heavy tiles first
    const int q0 = qt * 128;
    const int nkt = 2 * qt + 2;

    const size_t qk_off = (size_t)bh * SEQ * HD;
    const size_t vt_off = (size_t)bh * HD * SEQ;

#pragma unroll
    for (int t = 0; t < 4; t++) {
        int idx = tid + t * 256;
        int row = idx >> 3, c16 = idx & 7;
        uint32_t sw = (uint32_t)(row * 128 + ((c16 ^ (row & 7)) << 4));
        CPASYNC16(sb + sw, s_qhi + qk_off + (size_t)(q0 + row) * HD + c16 * 8);
        CPASYNC16(sb + 16384u + sw, s_qlo + qk_off + (size_t)(q0 + row) * HD + c16 * 8);
    }
    {
        uint32_t d0 = sb + 32768u;
        at_stage64(d0,           s_khi + qk_off, HD, tid);
        at_stage64(d0 + 8192u,   s_klo + qk_off, HD, tid);
        at_stage64(d0 + 16384u,  s_vthi + vt_off, SEQ, tid);
        at_stage64(d0 + 24576u,  s_vtlo + vt_off, SEQ, tid);
    }
    asm volatile("cp.async.commit_group;" ::: "memory");

    float O[8][4];
#pragma unroll
    for (int nf = 0; nf < 8; nf++)
#pragma unroll
        for (int j = 0; j < 4; j++) O[nf][j] = 0.f;
    float m0 = -1e30f, m1 = -1e30f, l0 = 0.f, l1 = 0.f;

    const int r0g = q0 + wid * 16 + (lane >> 2);
    const int arow = wid * 16 + ((lane >> 3) & 1) * 8 + (lane & 7);
    const int brow_b = (lane & 7) + (lane >> 4) * 8;
    const int bsel = (lane >> 3) & 1;
    const int asel = lane >> 4;

    for (int kt = 0; kt < nkt; kt++) {
        const int p = kt & 1;
        const int k0 = kt * 64;
        asm volatile("cp.async.wait_group 0;" ::: "memory");
        __syncthreads();
        if (kt + 1 < nkt) {
            uint32_t dn = sb + 32768u + (uint32_t)(p ^ 1) * 32768u;
            int kn = (kt + 1) * 64;
            at_stage64(dn,          s_khi + qk_off + (size_t)kn * HD, HD, tid);
            at_stage64(dn + 8192u,  s_klo + qk_off + (size_t)kn * HD, HD, tid);
            at_stage64(dn + 16384u, s_vthi + vt_off + kn, SEQ, tid);
            at_stage64(dn + 24576u, s_vtlo + vt_off + kn, SEQ, tid);
            asm volatile("cp.async.commit_group;" ::: "memory");
        }

        if (q0 + wid * 16 + 15 < k0) continue;   // fully masked for this warp

        const uint32_t kb = sb + 32768u + (uint32_t)p * 32768u;

        float S[8][4];
#pragma unroll
        for (int nf = 0; nf < 8; nf++)
#pragma unroll
            for (int j = 0; j < 4; j++) S[nf][j] = 0.f;
#pragma unroll
        for (int kh = 0; kh < 4; kh++) {
            int ac16 = 2 * kh + asel;
            uint32_t aoff = (uint32_t)(arow * 128 + ((ac16 ^ (arow & 7)) << 4));
            uint32_t qh[4], ql[4];
            LDMX4(qh, sb + aoff);
            LDMX4(ql, sb + 16384u + aoff);
            int bc16 = 2 * kh + bsel;
#pragma unroll
            for (int bp = 0; bp < 4; bp++) {
                int brow = bp * 16 + brow_b;
                uint32_t boff = (uint32_t)(brow * 128 + ((bc16 ^ (brow & 7)) << 4));
                uint32_t th[4], tl[4];
                LDMX4(th, kb + boff);
                LDMX4(tl, kb + 8192u + boff);
                MMA16816(S[2*bp],   qh, th[0], th[1]);
                MMA16816(S[2*bp+1], qh, th[2], th[3]);
                MMA16816(S[2*bp],   qh, tl[0], tl[1]);
                MMA16816(S[2*bp+1], qh, tl[2], tl[3]);
                MMA16816(S[2*bp],   ql, th[0], th[1]);
                MMA16816(S[2*bp+1], ql, th[2], th[3]);
            }
        }

        // scale into base-2 domain + causal mask
        const bool msk = (k0 >= q0);
#pragma unroll
        for (int nf = 0; nf < 8; nf++)
#pragma unroll
            for (int j = 0; j < 4; j++) {
                float sv = S[nf][j] * SCL2;
                if (msk) {
                    int col = k0 + nf * 8 + (lane & 3) * 2 + (j & 1);
                    int row = (j < 2) ? r0g : r0g + 8;
                    if (col > row) sv = -1e30f;
                }
                S[nf][j] = sv;
            }

        float tm0 = -1e30f, tm1 = -1e30f;
#pragma unroll
        for (int nf = 0; nf < 8; nf++) {
            tm0 = fmaxf(tm0, fmaxf(S[nf][0], S[nf][1]));
            tm1 = fmaxf(tm1, fmaxf(S[nf][2], S[nf][3]));
        }
        tm0 = fmaxf(tm0, __shfl_xor_sync(0xffffffffu, tm0, 1));
        tm0 = fmaxf(tm0, __shfl_xor_sync(0xffffffffu, tm0, 2));
        tm1 = fmaxf(tm1, __shfl_xor_sync(0xffffffffu, tm1, 1));
        tm1 = fmaxf(tm1, __shfl_xor_sync(0xffffffffu, tm1, 2));
        float mn0 = fmaxf(m0, tm0), mn1 = fmaxf(m1, tm1);
        float f0 = exp2f(m0 - mn0), f1 = exp2f(m1 - mn1);
        m0 = mn0; m1 = mn1;
        float rs0 = 0.f, rs1 = 0.f;
#pragma unroll
        for (int nf = 0; nf < 8; nf++) {
            S[nf][0] = exp2f(S[nf][0] - mn0); rs0 += S[nf][0];
            S[nf][1] = exp2f(S[nf][1] - mn0); rs0 += S[nf][1];
            S[nf][2] = exp2f(S[nf][2] - mn1); rs1 += S[nf][2];
            S[nf][3] = exp2f(S[nf][3] - mn1); rs1 += S[nf][3];
        }
        rs0 += __shfl_xor_sync(0xffffffffu, rs0, 1);
        rs0 += __shfl_xor_sync(0xffffffffu, rs0, 2);
        rs1 += __shfl_xor_sync(0xffffffffu, rs1, 1);
        rs1 += __shfl_xor_sync(0xffffffffu, rs1, 2);
        l0 = l0 * f0 + rs0;
        l1 = l1 * f1 + rs1;
#pragma unroll
        for (int nf = 0; nf < 8; nf++) {
            O[nf][0] *= f0; O[nf][1] *= f0;
            O[nf][2] *= f1; O[nf][3] *= f1;
        }

#pragma unroll
        for (int kk = 0; kk < 4; kk++) {
            uint32_t ah[4], al[4];
            split2(S[2*kk][0],   S[2*kk][1],   ah[0], al[0]);
            split2(S[2*kk][2],   S[2*kk][3],   ah[1], al[1]);
            split2(S[2*kk+1][0], S[2*kk+1][1], ah[2], al[2]);
            split2(S[2*kk+1][2], S[2*kk+1][3], ah[3], al[3]);
            int bc16 = 2 * kk + bsel;
#pragma unroll
            for (int bp = 0; bp < 4; bp++) {
                int brow = bp * 16 + brow_b;
                uint32_t boff = (uint32_t)(brow * 128 + ((bc16 ^ (brow & 7)) << 4));
                uint32_t vh[4], vl[4];
                LDMX4(vh, kb + 16384u + boff);
                LDMX4(vl, kb + 24576u + boff);
                MMA16816(O[2*bp],   ah, vh[0], vh[1]);
                MMA16816(O[2*bp+1], ah, vh[2], vh[3]);
                MMA16816(O[2*bp],   ah, vl[0], vl[1]);
                MMA16816(O[2*bp+1], ah, vl[2], vl[3]);
                MMA16816(O[2*bp],   al, vh[0], vh[1]);
                MMA16816(O[2*bp+1], al, vh[2], vh[3]);
            }
        }
    }

    const int b = bh >> 4, h = bh & 15;
    const float inv0 = 1.0f / l0, inv1 = 1.0f / l1;
    const size_t mrow0 = (size_t)(b * SEQ + r0g) * DM;
    const size_t mrow1 = (size_t)(b * SEQ + r0g + 8) * DM;
    const int colb = h * HD + (lane & 3) * 2;
#pragma unroll
    for (int nf = 0; nf < 8; nf++) {
        int col = colb + nf * 8;
        uint32_t hi, lo;
        split2(O[nf][0] * inv0, O[nf][1] * inv0, hi, lo);
        *(uint32_t*)(s_ahi + mrow0 + col) = hi;
        *(uint32_t*)(s_alo + mrow0 + col) = lo;
        split2(O[nf][2] * inv1, O[nf][3] * inv1, hi, lo);
        *(uint32_t*)(s_ahi + mrow1 + col) = hi;
        *(uint32_t*)(s_alo + mrow1 + col) = lo;
    }
}

// ---------------------------------------------------------------------------
extern "C" void kernel_launch(void* const* d_in, const int* in_sizes, int n_in,
                              void* d_out, int out_size) {
    (void)out_size;
    const float* x = (const float*)d_in[0];
    const float* w_qkv = (const float*)d_in[1];
    const float* w_out = (const float*)d_in[2];
    for (int i = 0; i < n_in; i++) {
        if (in_sizes[i] == 8388608)      x     = (const float*)d_in[i];
        else if (in_sizes[i] == 3145728) w_qkv = (const float*)d_in[i];
        else if (in_sizes[i] == 1048576) w_out = (const float*)d_in[i];
    }
    float* out = (float*)d_out;

    void *p_xhi, *p_xlo, *p_whi, *p_wlo, *p_ohi, *p_olo, *p_ahi, *p_alo;
    cudaGetSymbolAddress(&p_xhi, s_xhi);
    cudaGetSymbolAddress(&p_xlo, s_xlo);
    cudaGetSymbolAddress(&p_whi, s_whi);
    cudaGetSymbolAddress(&p_wlo, s_wlo);
    cudaGetSymbolAddress(&p_ohi, s_ohi);
    cudaGetSymbolAddress(&p_olo, s_olo);
    cudaGetSymbolAddress(&p_ahi, s_ahi);
    cudaGetSymbolAddress(&p_alo, s_alo);

    cudaFuncSetAttribute(gemm_mma, cudaFuncAttributeMaxDynamicSharedMemorySize, GEMM_SMEM);
    cudaFuncSetAttribute(attn_mma, cudaFuncAttributeMaxDynamicSharedMemorySize, AT_SMEM);

    cvt_split3<<<(N_X + N_W + N_O) / 256, 256>>>(x, w_qkv, w_out);

    gemm_mma<<<dim3(3*DM/128, MTOT/128), 256, GEMM_SMEM>>>(
        (const __nv_bfloat16*)p_xhi, (const __nv_bfloat16*)p_xlo,
        (const __nv_bfloat16*)p_whi, (const __nv_bfloat16*)p_wlo, nullptr, 1);

    transpose_v<<<dim3(BATCH*NH, SEQ/64), 256>>>();

    attn_mma<<<dim3(BATCH*NH, SEQ/128), 256, AT_SMEM>>>();

    gemm_mma<<<dim3(DM/128, MTOT/128), 256, GEMM_SMEM>>>(
        (const __nv_bfloat16*)p_ahi, (const __nv_bfloat16*)p_alo,
        (const __nv_bfloat16*)p_ohi, (const __nv_bfloat16*)p_olo, out, 0);
}